// round 1
// baseline (speedup 1.0000x reference)
#include <cuda_runtime.h>
#include <cstdint>

#define NN 50000
#define NE 640000
#define NF 128
#define EF 128
#define UF 64
#define HID 256
#define NG 64
#define NOUT 128

// Scratch (device globals: allocation-free per harness rules)
__device__ float g_pre1[(size_t)NN * HID];   // x @ W1_top + b1
__device__ float g_agg[(size_t)NN * HID];    // scatter-sum of edge messages
__device__ float g_cnt[NN];                  // per-node in-degree
__device__ int   g_idx64;                    // 1 if indices are int64, 0 if int32

// ---------------------------------------------------------------------------
// dtype detect: reference asks for int64 but JAX without x64 produces int32.
// If int64, every odd 32-bit word (high half, values < 2^31) is zero.
// ---------------------------------------------------------------------------
__global__ void detect_kernel(const unsigned int* __restrict__ ei) {
    if (threadIdx.x == 0 && blockIdx.x == 0) {
        int is64 = 1;
        for (int i = 0; i < 32; ++i)
            if (ei[2 * i + 1] != 0u) { is64 = 0; break; }
        g_idx64 = is64;
    }
}

__global__ void zero_kernel() {
    long long tid = (long long)blockIdx.x * blockDim.x + threadIdx.x;
    long long stride = (long long)gridDim.x * blockDim.x;
    float4* a4 = reinterpret_cast<float4*>(g_agg);
    const long long n4 = (long long)NN * HID / 4;
    for (long long i = tid; i < n4; i += stride) a4[i] = make_float4(0.f, 0.f, 0.f, 0.f);
    for (long long i = tid; i < NN; i += stride) g_cnt[i] = 0.f;
}

// ---------------------------------------------------------------------------
// Shared GEMM building blocks: 64(M) x 256(N) block tile, 256 threads,
// 8x8 micro-tile. Thread map: r = tx>>5 (m0=r*8), c = tx&31 (n0=c*8).
// ---------------------------------------------------------------------------
__device__ __forceinline__ void load_b256(float* __restrict__ sB,
                                          const float* __restrict__ W, int tx) {
    // 32 rows x 256 cols, vectorized
#pragma unroll
    for (int v = tx; v < 2048; v += 256) {
        int row = v >> 6, colv = v & 63;
        *reinterpret_cast<float4*>(sB + row * 256 + colv * 4) =
            *reinterpret_cast<const float4*>(W + row * 256 + colv * 4);
    }
}

__device__ __forceinline__ void load_b128(float* __restrict__ sB,
                                          const float* __restrict__ W, int tx) {
    // 32 rows x 128 cols
#pragma unroll
    for (int v = tx; v < 1024; v += 256) {
        int row = v >> 5, colv = v & 31;
        *reinterpret_cast<float4*>(sB + row * 128 + colv * 4) =
            *reinterpret_cast<const float4*>(W + row * 128 + colv * 4);
    }
}

template <int LDA>
__device__ __forceinline__ void gemm_chunk(const float* __restrict__ sA,
                                           const float* __restrict__ sB,
                                           int m0, int n0, int kbase,
                                           float acc[8][8]) {
#pragma unroll
    for (int kk = 0; kk < 32; ++kk) {
        const int k = kbase + kk;
        float a[8];
#pragma unroll
        for (int i = 0; i < 8; ++i) a[i] = sA[(m0 + i) * LDA + k];  // warp-broadcast
        float4 bv0 = *reinterpret_cast<const float4*>(sB + kk * 256 + n0);
        float4 bv1 = *reinterpret_cast<const float4*>(sB + kk * 256 + n0 + 4);
        float b[8] = {bv0.x, bv0.y, bv0.z, bv0.w, bv1.x, bv1.y, bv1.z, bv1.w};
#pragma unroll
        for (int i = 0; i < 8; ++i)
#pragma unroll
            for (int j = 0; j < 8; ++j) acc[i][j] += a[i] * b[j];
    }
}

// ---------------------------------------------------------------------------
// pre1 = x @ W1[0:128,:] + b1      [NN, HID]
// ---------------------------------------------------------------------------
__global__ __launch_bounds__(256) void pre1_kernel(const float* __restrict__ x,
                                                   const float* __restrict__ W1,
                                                   const float* __restrict__ b1) {
    extern __shared__ float smem[];
    float* sA = smem;             // 64*128
    float* sB = sA + 64 * 128;    // 32*256
    const int tx = threadIdx.x;
    const int bm = blockIdx.x * 64;

#pragma unroll
    for (int v = tx; v < 2048; v += 256) {
        int m = v >> 5, cv = v & 31;
        int mg = min(bm + m, NN - 1);
        *reinterpret_cast<float4*>(sA + m * 128 + cv * 4) =
            *reinterpret_cast<const float4*>(x + (long long)mg * NF + cv * 4);
    }
    __syncthreads();

    const int r = tx >> 5, c = tx & 31;
    const int m0 = r * 8, n0 = c * 8;
    float acc[8][8];
#pragma unroll
    for (int i = 0; i < 8; ++i)
#pragma unroll
        for (int j = 0; j < 8; ++j) acc[i][j] = 0.f;

    for (int kc = 0; kc < 4; ++kc) {
        load_b256(sB, W1 + kc * 32 * 256, tx);
        __syncthreads();
        gemm_chunk<128>(sA, sB, m0, n0, kc * 32, acc);
        __syncthreads();
    }

    float4 bb0 = *reinterpret_cast<const float4*>(b1 + n0);
    float4 bb1 = *reinterpret_cast<const float4*>(b1 + n0 + 4);
    float bb[8] = {bb0.x, bb0.y, bb0.z, bb0.w, bb1.x, bb1.y, bb1.z, bb1.w};
#pragma unroll
    for (int i = 0; i < 8; ++i) {
        int mg = bm + m0 + i;
        if (mg < NN) {
            float4 o0, o1;
            o0.x = acc[i][0] + bb[0]; o0.y = acc[i][1] + bb[1];
            o0.z = acc[i][2] + bb[2]; o0.w = acc[i][3] + bb[3];
            o1.x = acc[i][4] + bb[4]; o1.y = acc[i][5] + bb[5];
            o1.z = acc[i][6] + bb[6]; o1.w = acc[i][7] + bb[7];
            *reinterpret_cast<float4*>(g_pre1 + (long long)mg * HID + n0) = o0;
            *reinterpret_cast<float4*>(g_pre1 + (long long)mg * HID + n0 + 4) = o1;
        }
    }
}

// ---------------------------------------------------------------------------
// Edge kernel: per 64-edge tile:
//   h1 = relu(pre1[row] + ea @ W1[128:256,:])
//   msg = h1 @ W2 + b2   -> atomicAdd into g_agg[col], count into g_cnt
// ---------------------------------------------------------------------------
__global__ __launch_bounds__(256) void edge_kernel(const float* __restrict__ ea,
                                                   const void* __restrict__ eidx,
                                                   const float* __restrict__ W1,
                                                   const float* __restrict__ W2,
                                                   const float* __restrict__ b2) {
    extern __shared__ float smem[];
    float* sA = smem;               // 64*128 (edge_attr tile)
    float* sH = sA + 64 * 128;      // 64*256 (h1)
    float* sB = sH + 64 * 256;      // 32*256 (weight chunk)
    __shared__ int sRow[64], sCol[64];

    const int tx = threadIdx.x;
    const int bm = blockIdx.x * 64;
    const int is64 = g_idx64;

    if (tx < 64) {
        long long e = bm + tx;
        int rr, cc;
        if (is64) {
            rr = (int)reinterpret_cast<const long long*>(eidx)[e];
            cc = (int)reinterpret_cast<const long long*>(eidx)[NE + e];
        } else {
            rr = reinterpret_cast<const int*>(eidx)[e];
            cc = reinterpret_cast<const int*>(eidx)[NE + e];
        }
        sRow[tx] = rr; sCol[tx] = cc;
        atomicAdd(&g_cnt[cc], 1.0f);
    }
#pragma unroll
    for (int v = tx; v < 2048; v += 256) {
        int m = v >> 5, cv = v & 31;
        *reinterpret_cast<float4*>(sA + m * 128 + cv * 4) =
            *reinterpret_cast<const float4*>(ea + (long long)(bm + m) * EF + cv * 4);
    }
    __syncthreads();

    const int r = tx >> 5, c = tx & 31;
    const int m0 = r * 8, n0 = c * 8;
    float acc[8][8];
#pragma unroll
    for (int i = 0; i < 8; ++i)
#pragma unroll
        for (int j = 0; j < 8; ++j) acc[i][j] = 0.f;

    // GEMM1: ea @ W1[128:256,:]  (K = 128)
    for (int kc = 0; kc < 4; ++kc) {
        load_b256(sB, W1 + (128 + kc * 32) * 256, tx);
        __syncthreads();
        gemm_chunk<128>(sA, sB, m0, n0, kc * 32, acc);
        __syncthreads();
    }

    // epilogue 1: + pre1[row] (has b1), ReLU, stage into sH; reset acc
#pragma unroll
    for (int i = 0; i < 8; ++i) {
        const float* p = g_pre1 + (long long)sRow[m0 + i] * HID + n0;
        float4 p0 = *reinterpret_cast<const float4*>(p);
        float4 p1 = *reinterpret_cast<const float4*>(p + 4);
        float pr[8] = {p0.x, p0.y, p0.z, p0.w, p1.x, p1.y, p1.z, p1.w};
#pragma unroll
        for (int j = 0; j < 8; ++j) {
            sH[(m0 + i) * 256 + n0 + j] = fmaxf(acc[i][j] + pr[j], 0.f);
            acc[i][j] = 0.f;
        }
    }

    // GEMM2: h1 @ W2  (K = 256)
    for (int kc = 0; kc < 8; ++kc) {
        load_b256(sB, W2 + kc * 32 * 256, tx);
        __syncthreads();   // also orders sH writes above before first read
        gemm_chunk<256>(sH, sB, m0, n0, kc * 32, acc);
        __syncthreads();
    }

    // epilogue 2: + b2, atomic scatter-add into g_agg[col]
    float4 bb0 = *reinterpret_cast<const float4*>(b2 + n0);
    float4 bb1 = *reinterpret_cast<const float4*>(b2 + n0 + 4);
    float bb[8] = {bb0.x, bb0.y, bb0.z, bb0.w, bb1.x, bb1.y, bb1.z, bb1.w};
#pragma unroll
    for (int i = 0; i < 8; ++i) {
        float* dst = g_agg + (long long)sCol[m0 + i] * HID + n0;
#pragma unroll
        for (int j = 0; j < 8; ++j) atomicAdd(dst + j, acc[i][j] + bb[j]);
    }
}

// ---------------------------------------------------------------------------
// Node kernel: z = [x || agg/cnt || u[batch]] (448), out = relu(z@W3+b3)@W4+b4
// ---------------------------------------------------------------------------
__global__ __launch_bounds__(256) void node_kernel(const float* __restrict__ x,
                                                   const float* __restrict__ u,
                                                   const void* __restrict__ batch,
                                                   const float* __restrict__ W3,
                                                   const float* __restrict__ b3,
                                                   const float* __restrict__ W4,
                                                   const float* __restrict__ b4,
                                                   float* __restrict__ out) {
    extern __shared__ float smem[];
    float* sZ = smem;               // 64*448
    float* sH = sZ + 64 * 448;      // 64*256
    float* sB = sH + 64 * 256;      // 32*256
    __shared__ float sInv[64];
    __shared__ int sBat[64];

    const int tx = threadIdx.x;
    const int bm = blockIdx.x * 64;
    const int is64 = g_idx64;

    if (tx < 64) {
        int mg = min(bm + tx, NN - 1);
        sInv[tx] = 1.f / fmaxf(g_cnt[mg], 1.f);
        sBat[tx] = is64 ? (int)reinterpret_cast<const long long*>(batch)[mg]
                        : reinterpret_cast<const int*>(batch)[mg];
    }
    __syncthreads();

    // stage z: x part
#pragma unroll
    for (int v = tx; v < 2048; v += 256) {
        int m = v >> 5, cv = v & 31;
        int mg = min(bm + m, NN - 1);
        *reinterpret_cast<float4*>(sZ + m * 448 + cv * 4) =
            *reinterpret_cast<const float4*>(x + (long long)mg * NF + cv * 4);
    }
    // agg/cnt part
#pragma unroll
    for (int v = tx; v < 4096; v += 256) {
        int m = v >> 6, cv = v & 63;
        int mg = min(bm + m, NN - 1);
        float4 a = *reinterpret_cast<const float4*>(g_agg + (long long)mg * HID + cv * 4);
        float inv = sInv[m];
        a.x *= inv; a.y *= inv; a.z *= inv; a.w *= inv;
        *reinterpret_cast<float4*>(sZ + m * 448 + 128 + cv * 4) = a;
    }
    // u[batch] part
#pragma unroll
    for (int v = tx; v < 1024; v += 256) {
        int m = v >> 4, cv = v & 15;
        *reinterpret_cast<float4*>(sZ + m * 448 + 384 + cv * 4) =
            *reinterpret_cast<const float4*>(u + sBat[m] * UF + cv * 4);
    }
    __syncthreads();

    const int r = tx >> 5, c = tx & 31;
    const int m0 = r * 8, n0 = c * 8;
    float acc[8][8];
#pragma unroll
    for (int i = 0; i < 8; ++i)
#pragma unroll
        for (int j = 0; j < 8; ++j) acc[i][j] = 0.f;

    // layer 3: z @ W3  (K = 448)
    for (int kc = 0; kc < 14; ++kc) {
        load_b256(sB, W3 + kc * 32 * 256, tx);
        __syncthreads();
        gemm_chunk<448>(sZ, sB, m0, n0, kc * 32, acc);
        __syncthreads();
    }

    // relu(acc + b3) -> sH
    {
        float4 bb0 = *reinterpret_cast<const float4*>(b3 + n0);
        float4 bb1 = *reinterpret_cast<const float4*>(b3 + n0 + 4);
        float bb[8] = {bb0.x, bb0.y, bb0.z, bb0.w, bb1.x, bb1.y, bb1.z, bb1.w};
#pragma unroll
        for (int i = 0; i < 8; ++i)
#pragma unroll
            for (int j = 0; j < 8; ++j)
                sH[(m0 + i) * 256 + n0 + j] = fmaxf(acc[i][j] + bb[j], 0.f);
    }

    // layer 4: sH @ W4  (K = 256, Nout = 128): micro-tile 8x4
    const int n4 = c * 4;
    float acc2[8][4];
#pragma unroll
    for (int i = 0; i < 8; ++i)
#pragma unroll
        for (int j = 0; j < 4; ++j) acc2[i][j] = 0.f;

    for (int kc = 0; kc < 8; ++kc) {
        load_b128(sB, W4 + kc * 32 * 128, tx);
        __syncthreads();   // also orders sH writes above
#pragma unroll
        for (int kk = 0; kk < 32; ++kk) {
            const int k = kc * 32 + kk;
            float a[8];
#pragma unroll
            for (int i = 0; i < 8; ++i) a[i] = sH[(m0 + i) * 256 + k];
            float4 bv = *reinterpret_cast<const float4*>(sB + kk * 128 + n4);
            float b[4] = {bv.x, bv.y, bv.z, bv.w};
#pragma unroll
            for (int i = 0; i < 8; ++i)
#pragma unroll
                for (int j = 0; j < 4; ++j) acc2[i][j] += a[i] * b[j];
        }
        __syncthreads();
    }

    float4 b4v = *reinterpret_cast<const float4*>(b4 + n4);
#pragma unroll
    for (int i = 0; i < 8; ++i) {
        int mg = bm + m0 + i;
        if (mg < NN) {
            float4 o;
            o.x = acc2[i][0] + b4v.x; o.y = acc2[i][1] + b4v.y;
            o.z = acc2[i][2] + b4v.z; o.w = acc2[i][3] + b4v.w;
            *reinterpret_cast<float4*>(out + (long long)mg * NOUT + n4) = o;
        }
    }
}

// ---------------------------------------------------------------------------
extern "C" void kernel_launch(void* const* d_in, const int* in_sizes, int n_in,
                              void* d_out, int out_size) {
    const float* x  = (const float*)d_in[0];
    const void*  ei = d_in[1];
    const float* ea = (const float*)d_in[2];
    const float* u  = (const float*)d_in[3];
    const void*  bt = d_in[4];
    const float* W1 = (const float*)d_in[5];
    const float* b1 = (const float*)d_in[6];
    const float* W2 = (const float*)d_in[7];
    const float* b2 = (const float*)d_in[8];
    const float* W3 = (const float*)d_in[9];
    const float* b3 = (const float*)d_in[10];
    const float* W4 = (const float*)d_in[11];
    const float* b4 = (const float*)d_in[12];
    float* out = (float*)d_out;

    const int smem_pre1 = (64 * 128 + 32 * 256) * 4;               // 64 KB
    const int smem_edge = (64 * 128 + 64 * 256 + 32 * 256) * 4;    // 128 KB
    const int smem_node = (64 * 448 + 64 * 256 + 32 * 256) * 4;    // 208 KB

    cudaFuncSetAttribute(pre1_kernel, cudaFuncAttributeMaxDynamicSharedMemorySize, smem_pre1);
    cudaFuncSetAttribute(edge_kernel, cudaFuncAttributeMaxDynamicSharedMemorySize, smem_edge);
    cudaFuncSetAttribute(node_kernel, cudaFuncAttributeMaxDynamicSharedMemorySize, smem_node);

    detect_kernel<<<1, 32>>>((const unsigned int*)ei);
    zero_kernel<<<592, 256>>>();
    pre1_kernel<<<(NN + 63) / 64, 256, smem_pre1>>>(x, W1, b1);
    edge_kernel<<<NE / 64, 256, smem_edge>>>(ea, ei, W1, W2, b2);
    node_kernel<<<(NN + 63) / 64, 256, smem_node>>>(x, u, bt, W3, b3, W4, b4, out);
}

// round 4
// speedup vs baseline: 2.4848x; 2.4848x over previous
#include <cuda_runtime.h>
#include <cstdint>

#define NN 50000
#define NE 640000
#define NF 128
#define EF 128
#define UF 64
#define HID 256
#define NG 64
#define NOUT 128

// ---------------- device global scratch (allocation-free) ----------------
__device__ float g_pre1[(size_t)NN * HID];   // x @ W1[0:128] + b1
__device__ float g_pre3[(size_t)NN * HID];   // x @ W3[0:128]
__device__ float g_aggH[(size_t)NN * HID];   // scatter-sum of h1
__device__ float g_cnt[NN];
__device__ float g_W23[HID * HID];           // W2 @ W3[128:384]
__device__ float g_uW3[NG * HID];            // u[g] @ W3[384:448] + b3
__device__ float g_bW[HID];                  // b2 @ W3[128:384]
// W1_bot^T in mma.sync fragment layout: 8 K-chunks x {hi 4096, lo 4096} floats
__device__ float g_Bfrag[8 * 8192];
__device__ int   g_idx64;

// ---------------- helpers ----------------
__device__ __forceinline__ uint32_t smem_u32(const void* p) {
    uint32_t a;
    asm("{ .reg .u64 t; cvta.to.shared.u64 t, %1; cvt.u32.u64 %0, t; }" : "=r"(a) : "l"(p));
    return a;
}
__device__ __forceinline__ float tf32_rna(float x) {
    uint32_t u;
    asm("cvt.rna.tf32.f32 %0, %1;" : "=r"(u) : "f"(x));
    return __uint_as_float(u);
}
__device__ __forceinline__ void mma8(float d[4], uint32_t a0, uint32_t a1, uint32_t a2, uint32_t a3,
                                     uint32_t b0, uint32_t b1) {
    asm volatile("mma.sync.aligned.m16n8k8.row.col.f32.tf32.tf32.f32 "
                 "{%0,%1,%2,%3}, {%4,%5,%6,%7}, {%8,%9}, {%0,%1,%2,%3};"
                 : "+f"(d[0]), "+f"(d[1]), "+f"(d[2]), "+f"(d[3])
                 : "r"(a0), "r"(a1), "r"(a2), "r"(a3), "r"(b0), "r"(b1));
}

// ---------------- detect int64/int32 indices ----------------
__global__ void detect_kernel(const unsigned int* __restrict__ ei) {
    if (threadIdx.x == 0 && blockIdx.x == 0) {
        int is64 = 1;
        for (int i = 0; i < 32; ++i)
            if (ei[2 * i + 1] != 0u) { is64 = 0; break; }
        g_idx64 = is64;
    }
}

__global__ void zero_kernel() {
    long long tid = (long long)blockIdx.x * blockDim.x + threadIdx.x;
    long long stride = (long long)gridDim.x * blockDim.x;
    float4* a4 = reinterpret_cast<float4*>(g_aggH);
    const long long n4 = (long long)NN * HID / 4;
    for (long long i = tid; i < n4; i += stride) a4[i] = make_float4(0.f, 0.f, 0.f, 0.f);
    for (long long i = tid; i < NN; i += stride) g_cnt[i] = 0.f;
}

// ---------------- prep: W1_bot^T tf32 hi/lo fragment-layout images ----------------
// Fragment layout (m16n8k8.row.col, B operand): for K-chunk c (16 K each),
// s = (k>>3)&1, nt = n>>3, lane = (n&7)*4 + (k&3), reg = ((k&7)>=4).
// offset within chunk-plane: (s*32+nt)*64 + lane*2 + reg. Chunk block = [hi 4096][lo 4096].
__global__ void prep_w1bt_kernel(const float* __restrict__ W1) {
    int gid = blockIdx.x * blockDim.x + threadIdx.x;   // 0..32767
    if (gid >= 32768) return;
    int k = gid >> 8;        // 0..127
    int n = gid & 255;       // 0..255
    float v = W1[(size_t)(128 + k) * HID + n];
    float hi = tf32_rna(v);
    float lo = tf32_rna(v - hi);
    int c = k >> 4, s = (k >> 3) & 1, nt = n >> 3;
    int lane = (n & 7) * 4 + (k & 3);
    int reg = ((k & 7) >= 4) ? 1 : 0;
    int off = (s * 32 + nt) * 64 + lane * 2 + reg;
    g_Bfrag[c * 8192 + off] = hi;
    g_Bfrag[c * 8192 + 4096 + off] = lo;
}

// ---------------- prep: W23 = W2 @ W3[128:384] ----------------
__global__ void prep_w23_kernel(const float* __restrict__ W2, const float* __restrict__ W3) {
    int k = blockIdx.x;        // 0..255
    int n = threadIdx.x;       // 0..255
    float acc = 0.f;
    for (int j = 0; j < HID; ++j)
        acc += W2[(size_t)k * HID + j] * W3[(size_t)(128 + j) * HID + n];
    g_W23[k * HID + n] = acc;
}

// ---------------- prep: uW3[g] = u[g] @ W3[384:448] + b3 ; bW = b2 @ W3[128:384] ----------------
__global__ void prep_u_kernel(const float* __restrict__ u, const float* __restrict__ W3,
                              const float* __restrict__ b3, const float* __restrict__ b2) {
    int g = blockIdx.x;
    int n = threadIdx.x;
    if (g < NG) {
        float acc = b3[n];
        for (int j = 0; j < UF; ++j)
            acc += u[g * UF + j] * W3[(size_t)(384 + j) * HID + n];
        g_uW3[g * HID + n] = acc;
    } else {
        float acc = 0.f;
        for (int j = 0; j < HID; ++j)
            acc += b2[j] * W3[(size_t)(128 + j) * HID + n];
        g_bW[n] = acc;
    }
}

// ---------------- FFMA GEMM building blocks (64x256 tile, 256 threads) ----------------
__device__ __forceinline__ void load_b256(float* __restrict__ sB, const float* __restrict__ W, int tx) {
#pragma unroll
    for (int v = tx; v < 2048; v += 256) {
        int row = v >> 6, colv = v & 63;
        *reinterpret_cast<float4*>(sB + row * 256 + colv * 4) =
            *reinterpret_cast<const float4*>(W + row * 256 + colv * 4);
    }
}
__device__ __forceinline__ void load_b128(float* __restrict__ sB, const float* __restrict__ W, int tx) {
#pragma unroll
    for (int v = tx; v < 1024; v += 256) {
        int row = v >> 5, colv = v & 31;
        *reinterpret_cast<float4*>(sB + row * 128 + colv * 4) =
            *reinterpret_cast<const float4*>(W + row * 128 + colv * 4);
    }
}
template <int LDA>
__device__ __forceinline__ void gemm_chunk(const float* __restrict__ sA, const float* __restrict__ sB,
                                           int m0, int n0, int kbase, float acc[8][8]) {
#pragma unroll
    for (int kk = 0; kk < 32; ++kk) {
        const int k = kbase + kk;
        float a[8];
#pragma unroll
        for (int i = 0; i < 8; ++i) a[i] = sA[(m0 + i) * LDA + k];
        float4 bv0 = *reinterpret_cast<const float4*>(sB + kk * 256 + n0);
        float4 bv1 = *reinterpret_cast<const float4*>(sB + kk * 256 + n0 + 4);
        float b[8] = {bv0.x, bv0.y, bv0.z, bv0.w, bv1.x, bv1.y, bv1.z, bv1.w};
#pragma unroll
        for (int i = 0; i < 8; ++i)
#pragma unroll
            for (int j = 0; j < 8; ++j) acc[i][j] += a[i] * b[j];
    }
}

// ---------------- pre kernel: g_pre1 = x@W1[0:128]+b1 (y=0), g_pre3 = x@W3[0:128] (y=1) ----------------
__global__ __launch_bounds__(256) void pre_kernel(const float* __restrict__ x,
                                                  const float* __restrict__ W1,
                                                  const float* __restrict__ b1,
                                                  const float* __restrict__ W3) {
    extern __shared__ float smem[];
    float* sA = smem;             // 64*128
    float* sB = sA + 64 * 128;    // 32*256
    const int tx = threadIdx.x;
    const int bm = blockIdx.x * 64;
    const float* W = (blockIdx.y == 0) ? W1 : W3;
    const float* bias = (blockIdx.y == 0) ? b1 : nullptr;
    float* outp = (blockIdx.y == 0) ? g_pre1 : g_pre3;

#pragma unroll
    for (int v = tx; v < 2048; v += 256) {
        int m = v >> 5, cv = v & 31;
        int mg = min(bm + m, NN - 1);
        *reinterpret_cast<float4*>(sA + m * 128 + cv * 4) =
            *reinterpret_cast<const float4*>(x + (size_t)mg * NF + cv * 4);
    }
    __syncthreads();

    const int r = tx >> 5, c = tx & 31;
    const int m0 = r * 8, n0 = c * 8;
    float acc[8][8];
#pragma unroll
    for (int i = 0; i < 8; ++i)
#pragma unroll
        for (int j = 0; j < 8; ++j) acc[i][j] = 0.f;

    for (int kc = 0; kc < 4; ++kc) {
        load_b256(sB, W + (size_t)kc * 32 * 256, tx);
        __syncthreads();
        gemm_chunk<128>(sA, sB, m0, n0, kc * 32, acc);
        __syncthreads();
    }

    float bb[8];
    if (bias) {
        float4 b0 = *reinterpret_cast<const float4*>(bias + n0);
        float4 b1v = *reinterpret_cast<const float4*>(bias + n0 + 4);
        bb[0] = b0.x; bb[1] = b0.y; bb[2] = b0.z; bb[3] = b0.w;
        bb[4] = b1v.x; bb[5] = b1v.y; bb[6] = b1v.z; bb[7] = b1v.w;
    } else {
#pragma unroll
        for (int j = 0; j < 8; ++j) bb[j] = 0.f;
    }
#pragma unroll
    for (int i = 0; i < 8; ++i) {
        int mg = bm + m0 + i;
        if (mg < NN) {
            float4 o0, o1;
            o0.x = acc[i][0] + bb[0]; o0.y = acc[i][1] + bb[1];
            o0.z = acc[i][2] + bb[2]; o0.w = acc[i][3] + bb[3];
            o1.x = acc[i][4] + bb[4]; o1.y = acc[i][5] + bb[5];
            o1.z = acc[i][6] + bb[6]; o1.w = acc[i][7] + bb[7];
            *reinterpret_cast<float4*>(outp + (size_t)mg * HID + n0) = o0;
            *reinterpret_cast<float4*>(outp + (size_t)mg * HID + n0 + 4) = o1;
        }
    }
}

// ---------------- edge kernel: mma.sync tf32 3x-split ----------------
// Tile: 128 edges x 256 out, K=128. 512 threads = 16 warps (4x4), warp tile 32x64.
// h1 = relu(ea @ W1[128:256] + pre1[row]) ; red.v4 scatter into g_aggH[col] ; cnt++
#define OUT_LD 260   // padded sOut row stride (floats) for conflict-free epilogue
__global__ __launch_bounds__(512, 1) void edge_mma_kernel(const float* __restrict__ ea,
                                                          const void* __restrict__ eidx) {
    extern __shared__ float sm[];
    float* sAh = sm;              // 16384 floats (A hi, frag layout, full K)
    float* sAl = sm + 16384;      // 16384 floats (A lo)
    float* sB  = sm + 32768;      // 16384 floats: 2 bufs x [hi 4096 | lo 4096]
    __shared__ int sRow[128], sCol[128];

    const int tx = threadIdx.x;
    const int w = tx >> 5;
    const int lane = tx & 31;
    const int bm = blockIdx.x * 128;
    const int is64 = g_idx64;

    if (tx < 128) {
        long long e = bm + tx;
        int rr, cc;
        if (is64) {
            rr = (int)reinterpret_cast<const long long*>(eidx)[e];
            cc = (int)reinterpret_cast<const long long*>(eidx)[NE + e];
        } else {
            rr = reinterpret_cast<const int*>(eidx)[e];
            cc = reinterpret_cast<const int*>(eidx)[NE + e];
        }
        sRow[tx] = rr; sCol[tx] = cc;
        atomicAdd(&g_cnt[cc], 1.0f);
    }

    // ---- stage A (128 rows x 128 k) into hi/lo fragment layout ----
    {
        const int row = tx >> 2;
        const int kq = (tx & 3) * 32;
        const float* src = ea + (size_t)(bm + row) * EF + kq;
        const int mt = row >> 4;
        const int rbit = ((row & 15) >= 8) ? 2 : 0;
        const int lbase = (row & 7) * 4;
#pragma unroll
        for (int j = 0; j < 8; ++j) {
            float4 v = *reinterpret_cast<const float4*>(src + j * 4);
            float vv[4] = {v.x, v.y, v.z, v.w};
#pragma unroll
            for (int e = 0; e < 4; ++e) {
                int k = kq + j * 4 + e;
                int cch = k >> 4, s = (k >> 3) & 1;
                int reg = (((k & 7) >= 4) ? 1 : 0) * 2 + (rbit >> 1);
                int off = (((cch * 2 + s) * 8 + mt) * 128 + (lbase + (k & 3)) * 4 + reg);
                float hi = tf32_rna(vv[e]);
                sAh[off] = hi;
                sAl[off] = tf32_rna(vv[e] - hi);
            }
        }
    }

    // ---- cp.async B chunk loader (32 KB per chunk) ----
    const uint32_t sBu = smem_u32(sB);
#define ISSUE_B(c_, buf_) do { \
        const float4* gsrc = reinterpret_cast<const float4*>(g_Bfrag + (c_) * 8192); \
        uint32_t dbase = sBu + (buf_) * 8192 * 4; \
        _Pragma("unroll") \
        for (int i_ = 0; i_ < 4; ++i_) { \
            int idx_ = i_ * 512 + tx; \
            asm volatile("cp.async.cg.shared.global [%0], [%1], 16;" \
                :: "r"(dbase + idx_ * 16), "l"(gsrc + idx_) : "memory"); \
        } \
        asm volatile("cp.async.commit_group;" ::: "memory"); \
    } while (0)

    ISSUE_B(0, 0);

    const int warp_m = w >> 2, warp_n = w & 3;
    float acc[2][8][4];
#pragma unroll
    for (int mi = 0; mi < 2; ++mi)
#pragma unroll
        for (int ni = 0; ni < 8; ++ni)
#pragma unroll
            for (int q = 0; q < 4; ++q) acc[mi][ni][q] = 0.f;

    for (int c = 0; c < 8; ++c) {
        const int buf = c & 1;
        if (c < 7) {
            ISSUE_B(c + 1, buf ^ 1);
            asm volatile("cp.async.wait_group 1;" ::: "memory");
        } else {
            asm volatile("cp.async.wait_group 0;" ::: "memory");
        }
        __syncthreads();

        const float* bh = sB + buf * 8192;
        const float* bl = bh + 4096;
#pragma unroll
        for (int s = 0; s < 2; ++s) {
            const int agrp = (c * 2 + s) * 8 + warp_m * 2;
            uint4 ah0 = *reinterpret_cast<const uint4*>(sAh + (agrp + 0) * 128 + lane * 4);
            uint4 ah1 = *reinterpret_cast<const uint4*>(sAh + (agrp + 1) * 128 + lane * 4);
            uint4 al0 = *reinterpret_cast<const uint4*>(sAl + (agrp + 0) * 128 + lane * 4);
            uint4 al1 = *reinterpret_cast<const uint4*>(sAl + (agrp + 1) * 128 + lane * 4);
#pragma unroll
            for (int ni = 0; ni < 8; ++ni) {
                const int nt = warp_n * 8 + ni;
                const int boff = (s * 32 + nt) * 64 + lane * 2;
                uint2 b0 = *reinterpret_cast<const uint2*>(bh + boff);
                mma8(acc[0][ni], ah0.x, ah0.y, ah0.z, ah0.w, b0.x, b0.y);
                mma8(acc[1][ni], ah1.x, ah1.y, ah1.z, ah1.w, b0.x, b0.y);
                mma8(acc[0][ni], al0.x, al0.y, al0.z, al0.w, b0.x, b0.y);
                mma8(acc[1][ni], al1.x, al1.y, al1.z, al1.w, b0.x, b0.y);
                uint2 b1 = *reinterpret_cast<const uint2*>(bl + boff);
                mma8(acc[0][ni], ah0.x, ah0.y, ah0.z, ah0.w, b1.x, b1.y);
                mma8(acc[1][ni], ah1.x, ah1.y, ah1.z, ah1.w, b1.x, b1.y);
            }
        }
        __syncthreads();
    }
#undef ISSUE_B

    // ---- epilogue: acc -> padded smem, then per-row relu(+pre1) + red.v4 scatter ----
    float* sOut = sm;  // reuse (needs 128*OUT_LD = 33280 floats < 49152)
#pragma unroll
    for (int mi = 0; mi < 2; ++mi) {
        const int r0 = warp_m * 32 + mi * 16 + (lane >> 2);
#pragma unroll
        for (int ni = 0; ni < 8; ++ni) {
            const int cb = warp_n * 64 + ni * 8 + (lane & 3) * 2;
            *reinterpret_cast<float2*>(sOut + r0 * OUT_LD + cb) = make_float2(acc[mi][ni][0], acc[mi][ni][1]);
            *reinterpret_cast<float2*>(sOut + (r0 + 8) * OUT_LD + cb) = make_float2(acc[mi][ni][2], acc[mi][ni][3]);
        }
    }
    __syncthreads();

#pragma unroll
    for (int rr = 0; rr < 8; ++rr) {
        const int row = w * 8 + rr;
        const float* prow = g_pre1 + (size_t)sRow[row] * HID;
        float* arow = g_aggH + (size_t)sCol[row] * HID;
        const int j0 = lane * 8;
        float4 v0 = *reinterpret_cast<const float4*>(sOut + row * OUT_LD + j0);
        float4 v1 = *reinterpret_cast<const float4*>(sOut + row * OUT_LD + j0 + 4);
        float4 p0 = *reinterpret_cast<const float4*>(prow + j0);
        float4 p1 = *reinterpret_cast<const float4*>(prow + j0 + 4);
        float a0 = fmaxf(v0.x + p0.x, 0.f), a1 = fmaxf(v0.y + p0.y, 0.f);
        float a2 = fmaxf(v0.z + p0.z, 0.f), a3 = fmaxf(v0.w + p0.w, 0.f);
        float a4 = fmaxf(v1.x + p1.x, 0.f), a5 = fmaxf(v1.y + p1.y, 0.f);
        float a6 = fmaxf(v1.z + p1.z, 0.f), a7 = fmaxf(v1.w + p1.w, 0.f);
        asm volatile("red.global.add.v4.f32 [%0], {%1,%2,%3,%4};"
            :: "l"(arow + j0), "f"(a0), "f"(a1), "f"(a2), "f"(a3) : "memory");
        asm volatile("red.global.add.v4.f32 [%0], {%1,%2,%3,%4};"
            :: "l"(arow + j0 + 4), "f"(a4), "f"(a5), "f"(a6), "f"(a7) : "memory");
    }
}

// ---------------- node kernel: t = aggH@W23 ; L3 = relu(pre3 + t/cnt + uW3[batch] + bW*(cnt>0)) ; out = L3@W4 + b4
__global__ __launch_bounds__(256) void node_kernel(const void* __restrict__ batch,
                                                   const float* __restrict__ W4,
                                                   const float* __restrict__ b4,
                                                   float* __restrict__ out) {
    extern __shared__ float smem[];
    float* sA = smem;               // 64*256 aggH tile
    float* sH = sA + 64 * 256;      // 64*256
    float* sB = sH + 64 * 256;      // 32*256
    __shared__ float sInv[64], sFlag[64];
    __shared__ int sBat[64];

    const int tx = threadIdx.x;
    const int bm = blockIdx.x * 64;
    const int is64 = g_idx64;

    if (tx < 64) {
        int mg = min(bm + tx, NN - 1);
        float cnt = g_cnt[mg];
        sInv[tx] = 1.f / fmaxf(cnt, 1.f);
        sFlag[tx] = (cnt > 0.f) ? 1.f : 0.f;
        sBat[tx] = is64 ? (int)reinterpret_cast<const long long*>(batch)[mg]
                        : reinterpret_cast<const int*>(batch)[mg];
    }
#pragma unroll
    for (int v = tx; v < 4096; v += 256) {
        int mrow = v >> 6, cv = v & 63;
        int mg = min(bm + mrow, NN - 1);
        *reinterpret_cast<float4*>(sA + mrow * 256 + cv * 4) =
            *reinterpret_cast<const float4*>(g_aggH + (size_t)mg * HID + cv * 4);
    }
    __syncthreads();

    const int r = tx >> 5, c = tx & 31;
    const int m0 = r * 8, n0 = c * 8;
    float acc[8][8];
#pragma unroll
    for (int i = 0; i < 8; ++i)
#pragma unroll
        for (int j = 0; j < 8; ++j) acc[i][j] = 0.f;

    for (int kc = 0; kc < 8; ++kc) {
        load_b256(sB, g_W23 + (size_t)kc * 32 * 256, tx);
        __syncthreads();
        gemm_chunk<256>(sA, sB, m0, n0, kc * 32, acc);
        __syncthreads();
    }

    // L3 epilogue
#pragma unroll
    for (int i = 0; i < 8; ++i) {
        int mg = min(bm + m0 + i, NN - 1);
        float inv = sInv[m0 + i], fl = sFlag[m0 + i];
        const float* p3 = g_pre3 + (size_t)mg * HID + n0;
        const float* uw = g_uW3 + (size_t)sBat[m0 + i] * HID + n0;
        float4 p0 = *reinterpret_cast<const float4*>(p3);
        float4 p1 = *reinterpret_cast<const float4*>(p3 + 4);
        float4 u0 = *reinterpret_cast<const float4*>(uw);
        float4 u1 = *reinterpret_cast<const float4*>(uw + 4);
        float4 w0 = *reinterpret_cast<const float4*>(g_bW + n0);
        float4 w1 = *reinterpret_cast<const float4*>(g_bW + n0 + 4);
        float pp[8] = {p0.x, p0.y, p0.z, p0.w, p1.x, p1.y, p1.z, p1.w};
        float uu[8] = {u0.x, u0.y, u0.z, u0.w, u1.x, u1.y, u1.z, u1.w};
        float ww[8] = {w0.x, w0.y, w0.z, w0.w, w1.x, w1.y, w1.z, w1.w};
#pragma unroll
        for (int j = 0; j < 8; ++j)
            sH[(m0 + i) * 256 + n0 + j] = fmaxf(acc[i][j] * inv + pp[j] + uu[j] + ww[j] * fl, 0.f);
    }

    // layer 4: sH @ W4 (K=256, N=128)
    const int n4 = c * 4;
    float acc2[8][4];
#pragma unroll
    for (int i = 0; i < 8; ++i)
#pragma unroll
        for (int j = 0; j < 4; ++j) acc2[i][j] = 0.f;

    for (int kc = 0; kc < 8; ++kc) {
        load_b128(sB, W4 + (size_t)kc * 32 * 128, tx);
        __syncthreads();
#pragma unroll
        for (int kk = 0; kk < 32; ++kk) {
            const int k = kc * 32 + kk;
            float a[8];
#pragma unroll
            for (int i = 0; i < 8; ++i) a[i] = sH[(m0 + i) * 256 + k];
            float4 bv = *reinterpret_cast<const float4*>(sB + kk * 128 + n4);
            float b[4] = {bv.x, bv.y, bv.z, bv.w};
#pragma unroll
            for (int i = 0; i < 8; ++i)
#pragma unroll
                for (int j = 0; j < 4; ++j) acc2[i][j] += a[i] * b[j];
        }
        __syncthreads();
    }

    float4 b4v = *reinterpret_cast<const float4*>(b4 + n4);
#pragma unroll
    for (int i = 0; i < 8; ++i) {
        int mg = bm + m0 + i;
        if (mg < NN) {
            float4 o;
            o.x = acc2[i][0] + b4v.x; o.y = acc2[i][1] + b4v.y;
            o.z = acc2[i][2] + b4v.z; o.w = acc2[i][3] + b4v.w;
            *reinterpret_cast<float4*>(out + (size_t)mg * NOUT + n4) = o;
        }
    }
}

// ---------------------------------------------------------------------------
extern "C" void kernel_launch(void* const* d_in, const int* in_sizes, int n_in,
                              void* d_out, int out_size) {
    const float* x  = (const float*)d_in[0];
    const void*  ei = d_in[1];
    const float* ea = (const float*)d_in[2];
    const float* u  = (const float*)d_in[3];
    const void*  bt = d_in[4];
    const float* W1 = (const float*)d_in[5];
    const float* b1 = (const float*)d_in[6];
    const float* W2 = (const float*)d_in[7];
    const float* b2 = (const float*)d_in[8];
    const float* W3 = (const float*)d_in[9];
    const float* b3 = (const float*)d_in[10];
    const float* W4 = (const float*)d_in[11];
    const float* b4 = (const float*)d_in[12];
    float* out = (float*)d_out;

    const int smem_pre  = (64 * 128 + 32 * 256) * 4;              // 64 KB
    const int smem_edge = 49152 * 4;                              // 192 KB
    const int smem_node = (64 * 256 + 64 * 256 + 32 * 256) * 4;   // 160 KB

    cudaFuncSetAttribute(pre_kernel, cudaFuncAttributeMaxDynamicSharedMemorySize, smem_pre);
    cudaFuncSetAttribute(edge_mma_kernel, cudaFuncAttributeMaxDynamicSharedMemorySize, smem_edge);
    cudaFuncSetAttribute(node_kernel, cudaFuncAttributeMaxDynamicSharedMemorySize, smem_node);

    detect_kernel<<<1, 32>>>((const unsigned int*)ei);
    zero_kernel<<<1024, 256>>>();
    prep_w1bt_kernel<<<128, 256>>>(W1);
    prep_w23_kernel<<<256, 256>>>(W2, W3);
    prep_u_kernel<<<NG + 1, 256>>>(u, W3, b3, b2);
    pre_kernel<<<dim3((NN + 63) / 64, 2), 256, smem_pre>>>(x, W1, b1, W3);
    edge_mma_kernel<<<NE / 128, 512, smem_edge>>>(ea, ei);
    node_kernel<<<(NN + 63) / 64, 256, smem_node>>>(bt, W4, b4, out);
}

// round 8
// speedup vs baseline: 3.2552x; 1.3100x over previous
#include <cuda_runtime.h>
#include <cuda_bf16.h>
#include <cstdint>

#define NN 50000
#define NE 640000
#define NF 128
#define EF 128
#define UF 64
#define HID 256
#define NG 64
#define NOUT 128

// ---------------- device global scratch (allocation-free) ----------------
__device__ float g_pre1[(size_t)NN * HID];   // x @ W1[0:128] + b1
__device__ float g_pre3[(size_t)NN * HID];   // x @ W3[0:128]
__device__ float g_aggH[(size_t)NN * HID];   // scatter-sum of h1
__device__ float g_cnt[NN];
__device__ float g_W23[HID * HID];           // W2 @ W3[128:384]
__device__ float g_uW3[NG * HID];            // u[g] @ W3[384:448] + b3
__device__ float g_bW[HID];                  // b2 @ W3[128:384]
// bf16 hi/lo fragment-layout weight images (m16n8k16)
__device__ uint32_t g_BfE[8 * 4096];         // W1_bot^T  : 8 chunks x [hi 2048 | lo 2048] words
__device__ uint32_t g_BfP[8 * 8192];         // [W1top|W3top]^T : 8 chunks x [hi 4096 | lo 4096]
__device__ int   g_idx64;

// ---------------- helpers ----------------
__device__ __forceinline__ uint32_t smem_u32(const void* p) {
    uint32_t a;
    asm("{ .reg .u64 t; cvta.to.shared.u64 t, %1; cvt.u32.u64 %0, t; }" : "=r"(a) : "l"(p));
    return a;
}
// pack two floats to bf16x2: low 16 bits = first arg, high = second
__device__ __forceinline__ uint32_t pkbf(float lo, float hi) {
    uint32_t r;
    asm("cvt.rn.bf16x2.f32 %0, %1, %2;" : "=r"(r) : "f"(hi), "f"(lo));
    return r;
}
__device__ __forceinline__ float bfr(float v) {   // bf16 round-trip
    return __bfloat162float(__float2bfloat16(v));
}
__device__ __forceinline__ void mma16(float d[4], const uint32_t a[4], uint32_t b0, uint32_t b1) {
    asm volatile("mma.sync.aligned.m16n8k16.row.col.f32.bf16.bf16.f32 "
                 "{%0,%1,%2,%3}, {%4,%5,%6,%7}, {%8,%9}, {%0,%1,%2,%3};"
                 : "+f"(d[0]), "+f"(d[1]), "+f"(d[2]), "+f"(d[3])
                 : "r"(a[0]), "r"(a[1]), "r"(a[2]), "r"(a[3]), "r"(b0), "r"(b1));
}

// ---------------- detect int64/int32 indices ----------------
__global__ void detect_kernel(const unsigned int* __restrict__ ei) {
    if (threadIdx.x == 0 && blockIdx.x == 0) {
        int is64 = 1;
        for (int i = 0; i < 32; ++i)
            if (ei[2 * i + 1] != 0u) { is64 = 0; break; }
        g_idx64 = is64;
    }
}

__global__ void zero_kernel() {
    long long tid = (long long)blockIdx.x * blockDim.x + threadIdx.x;
    long long stride = (long long)gridDim.x * blockDim.x;
    float4* a4 = reinterpret_cast<float4*>(g_aggH);
    const long long n4 = (long long)NN * HID / 4;
    for (long long i = tid; i < n4; i += stride) a4[i] = make_float4(0.f, 0.f, 0.f, 0.f);
    for (long long i = tid; i < NN; i += stride) g_cnt[i] = 0.f;
}

// ---------------- prep: bf16 hi/lo fragment images for edge + pre GEMMs ----------------
// B fragment (m16n8k16 col): word = {B[2t][n], B[2t+1][n]}, reg b1 = +8 in k.
// word index within chunk plane: (nt*32 + lane)*2 + reg, lane = (n&7)*4 + t.
__global__ void prep_frag_kernel(const float* __restrict__ W1, const float* __restrict__ W3) {
    int gid = blockIdx.x * blockDim.x + threadIdx.x;   // 0..49151
    if (gid < 16384) {
        // edge image: W1_bot^T, K=128, N=256
        int kp = gid >> 8, n = gid & 255;
        int k0 = kp * 2;
        float v0 = W1[(size_t)(128 + k0) * HID + n];
        float v1 = W1[(size_t)(128 + k0 + 1) * HID + n];
        float h0 = bfr(v0), h1 = bfr(v1);
        int c = k0 >> 4, kk = k0 & 15, nt = n >> 3;
        int reg = (kk >= 8) ? 1 : 0;
        int lane = (n & 7) * 4 + ((kk & 7) >> 1);
        int idx = c * 4096 + (nt * 32 + lane) * 2 + reg;
        g_BfE[idx] = pkbf(h0, h1);
        g_BfE[idx + 2048] = pkbf(v0 - h0, v1 - h1);
    } else if (gid < 49152) {
        // pre image: [W1top | W3top], K=128, N=512
        int local = gid - 16384;
        int kp = local >> 9, n = local & 511;
        int k0 = kp * 2;
        const float* Wsrc = (n < 256) ? W1 : W3;
        int nc = n & 255;
        float v0 = Wsrc[(size_t)k0 * HID + nc];
        float v1 = Wsrc[(size_t)(k0 + 1) * HID + nc];
        float h0 = bfr(v0), h1 = bfr(v1);
        int c = k0 >> 4, kk = k0 & 15, nt = n >> 3;
        int reg = (kk >= 8) ? 1 : 0;
        int lane = (n & 7) * 4 + ((kk & 7) >> 1);
        int idx = c * 8192 + (nt * 32 + lane) * 2 + reg;
        g_BfP[idx] = pkbf(h0, h1);
        g_BfP[idx + 4096] = pkbf(v0 - h0, v1 - h1);
    }
}

// ---------------- prep: W23 = W2 @ W3[128:384] ----------------
__global__ void prep_w23_kernel(const float* __restrict__ W2, const float* __restrict__ W3) {
    int k = blockIdx.x, n = threadIdx.x;
    float acc = 0.f;
    for (int j = 0; j < HID; ++j)
        acc += W2[(size_t)k * HID + j] * W3[(size_t)(128 + j) * HID + n];
    g_W23[k * HID + n] = acc;
}

// ---------------- prep: uW3[g] = u[g]@W3[384:448]+b3 ; bW = b2@W3[128:384] ----------------
__global__ void prep_u_kernel(const float* __restrict__ u, const float* __restrict__ W3,
                              const float* __restrict__ b3, const float* __restrict__ b2) {
    int g = blockIdx.x, n = threadIdx.x;
    if (g < NG) {
        float acc = b3[n];
        for (int j = 0; j < UF; ++j)
            acc += u[g * UF + j] * W3[(size_t)(384 + j) * HID + n];
        g_uW3[g * HID + n] = acc;
    } else {
        float acc = 0.f;
        for (int j = 0; j < HID; ++j)
            acc += b2[j] * W3[(size_t)(128 + j) * HID + n];
        g_bW[n] = acc;
    }
}

// ---------------- shared MMA building blocks ----------------
// A fragment plane layout (packed bf16x2 words): idx = ((c*8+mt)*32 + (laneT ^ (mt<<2)))*4 + reg
//   laneT = (g&7)*4 + t, reg = (g>=8) + 2*(kk>=8), g=row&15, mt=row>>4, t=(kk&7)>>1
// Stage one row's 32-K span (kq..kq+31) into hi/lo planes.
__device__ __forceinline__ void stage_A(const float* __restrict__ src, int row, int kq,
                                        uint32_t* __restrict__ sAh, uint32_t* __restrict__ sAl) {
    float4 v[8];
#pragma unroll
    for (int j = 0; j < 8; ++j) v[j] = reinterpret_cast<const float4*>(src)[j];
    const float* vf = reinterpret_cast<const float*>(v);
    const int mt = row >> 4, g = row & 15;
    const int rbase = (g >= 8) ? 1 : 0;
    const int lbase = (g & 7) * 4;
#pragma unroll
    for (int pi = 0; pi < 16; ++pi) {
        float v0 = vf[2 * pi], v1 = vf[2 * pi + 1];
        float h0 = bfr(v0), h1 = bfr(v1);
        int k = kq + 2 * pi;
        int c = k >> 4, kk = k & 15;
        int reg = rbase + ((kk >= 8) ? 2 : 0);
        int lane2 = (lbase + ((kk & 7) >> 1)) ^ (mt << 2);
        int idx = ((c * 8 + mt) * 32 + lane2) * 4 + reg;
        sAh[idx] = pkbf(h0, h1);
        sAl[idx] = pkbf(v0 - h0, v1 - h1);
    }
}

// one K=16 chunk of 3-pass bf16 MMA; sB = chunk buffer [hi 2048 | lo 2048] words
__device__ __forceinline__ void mma_chunk(const uint32_t* __restrict__ sAh,
                                          const uint32_t* __restrict__ sAl,
                                          const uint32_t* __restrict__ sB,
                                          int c, int warp_m, int warp_n, int lane,
                                          float acc[2][8][4]) {
    uint32_t ah[2][4], al[2][4];
#pragma unroll
    for (int ii = 0; ii < 2; ++ii) {
        int mt = warp_m * 2 + ii;
        int base = ((c * 8 + mt) * 32 + (lane ^ (mt << 2))) * 4;
        *reinterpret_cast<uint4*>(ah[ii]) = *reinterpret_cast<const uint4*>(sAh + base);
        *reinterpret_cast<uint4*>(al[ii]) = *reinterpret_cast<const uint4*>(sAl + base);
    }
#pragma unroll
    for (int ni = 0; ni < 8; ++ni) {
        const int nt = warp_n * 8 + ni;
        uint2 bh = *reinterpret_cast<const uint2*>(sB + (nt * 32 + lane) * 2);
        uint2 bl = *reinterpret_cast<const uint2*>(sB + 2048 + (nt * 32 + lane) * 2);
        mma16(acc[0][ni], ah[0], bh.x, bh.y);
        mma16(acc[1][ni], ah[1], bh.x, bh.y);
        mma16(acc[0][ni], al[0], bh.x, bh.y);
        mma16(acc[1][ni], al[1], bh.x, bh.y);
        mma16(acc[0][ni], ah[0], bl.x, bl.y);
        mma16(acc[1][ni], ah[1], bl.x, bl.y);
    }
}

#define CP16(dst_u32, src_ptr) \
    asm volatile("cp.async.cg.shared.global [%0], [%1], 16;" :: "r"(dst_u32), "l"(src_ptr) : "memory")
#define CP_COMMIT() asm volatile("cp.async.commit_group;" ::: "memory")
#define CP_WAIT(n)  asm volatile("cp.async.wait_group %0;" :: "n"(n) : "memory")

// ---------------- pre kernel (bf16 MMA): tile 128 x 256, y selects N-half ----------------
// y=0: g_pre1 = x@W1top + b1 ; y=1: g_pre3 = x@W3top
__global__ __launch_bounds__(512, 1) void pre_mma_kernel(const float* __restrict__ x,
                                                         const float* __restrict__ b1) {
    extern __shared__ uint32_t smu[];
    uint32_t* sAh = smu;            // 8192 words
    uint32_t* sAl = smu + 8192;     // 8192
    uint32_t* sB  = smu + 16384;    // 2 x 4096

    const int tx = threadIdx.x;
    const int w = tx >> 5, lane = tx & 31;
    const int bm = blockIdx.x * 128;
    const int y = blockIdx.y;
    const uint32_t sBu = smem_u32(sB);

    // issue first B chunk
    {
        const uint32_t* src = g_BfP + 0 * 8192 + y * 2048;
#pragma unroll
        for (int seg = 0; seg < 2; ++seg)
            CP16(sBu + (seg * 2048 + tx * 4) * 4, src + seg * 4096 + tx * 4);
        CP_COMMIT();
    }

    // stage A
    {
        const int row = tx >> 2, kq = (tx & 3) * 32;
        int mg = min(bm + row, NN - 1);
        stage_A(x + (size_t)mg * NF + kq, row, kq, sAh, sAl);
    }

    const int warp_m = w >> 2, warp_n = w & 3;
    float acc[2][8][4];
#pragma unroll
    for (int mi = 0; mi < 2; ++mi)
#pragma unroll
        for (int ni = 0; ni < 8; ++ni)
#pragma unroll
            for (int q = 0; q < 4; ++q) acc[mi][ni][q] = 0.f;

    for (int c = 0; c < 8; ++c) {
        const int buf = c & 1;
        if (c < 7) {
            const uint32_t* src = g_BfP + (c + 1) * 8192 + y * 2048;
#pragma unroll
            for (int seg = 0; seg < 2; ++seg)
                CP16(sBu + ((buf ^ 1) * 4096 + seg * 2048 + tx * 4) * 4, src + seg * 4096 + tx * 4);
            CP_COMMIT();
            CP_WAIT(1);
        } else {
            CP_WAIT(0);
        }
        __syncthreads();
        mma_chunk(sAh, sAl, sB + buf * 4096, c, warp_m, warp_n, lane, acc);
        __syncthreads();
    }

    // register-direct epilogue
    const int g = lane >> 2, t = lane & 3;
    float* outp = (y == 0) ? g_pre1 : g_pre3;
#pragma unroll
    for (int mi = 0; mi < 2; ++mi) {
        int r0 = bm + warp_m * 32 + mi * 16 + g;
#pragma unroll
        for (int ni = 0; ni < 8; ++ni) {
            int cb = warp_n * 64 + ni * 8 + t * 2;
            float bb0 = 0.f, bb1 = 0.f;
            if (y == 0) { bb0 = b1[cb]; bb1 = b1[cb + 1]; }
            if (r0 < NN)
                *reinterpret_cast<float2*>(outp + (size_t)r0 * HID + cb) =
                    make_float2(acc[mi][ni][0] + bb0, acc[mi][ni][1] + bb1);
            if (r0 + 8 < NN)
                *reinterpret_cast<float2*>(outp + (size_t)(r0 + 8) * HID + cb) =
                    make_float2(acc[mi][ni][2] + bb0, acc[mi][ni][3] + bb1);
        }
    }
}

// ---------------- edge kernel (bf16 MMA): 128 edges x 256, K=128 ----------------
// h1 = relu(ea @ W1bot + pre1[row]) ; red.v4 scatter into g_aggH[col] ; cnt++
#define OLD 132   // padded sOut stride for the half-width epilogue
__global__ __launch_bounds__(512, 1) void edge_mma_kernel(const float* __restrict__ ea,
                                                          const void* __restrict__ eidx) {
    extern __shared__ uint32_t smu[];
    uint32_t* sAh = smu;
    uint32_t* sAl = smu + 8192;
    uint32_t* sB  = smu + 16384;
    __shared__ int sRow[128], sCol[128];

    const int tx = threadIdx.x;
    const int w = tx >> 5, lane = tx & 31;
    const int bm = blockIdx.x * 128;
    const int is64 = g_idx64;
    const uint32_t sBu = smem_u32(sB);

    // first B chunk
    {
        const uint32_t* src = g_BfE;
#pragma unroll
        for (int i = 0; i < 2; ++i)
            CP16(sBu + (i * 2048 + tx * 4) * 4, src + i * 2048 + tx * 4);
        CP_COMMIT();
    }

    if (tx < 128) {
        long long e = bm + tx;
        int rr, cc;
        if (is64) {
            rr = (int)reinterpret_cast<const long long*>(eidx)[e];
            cc = (int)reinterpret_cast<const long long*>(eidx)[NE + e];
        } else {
            rr = reinterpret_cast<const int*>(eidx)[e];
            cc = reinterpret_cast<const int*>(eidx)[NE + e];
        }
        sRow[tx] = rr; sCol[tx] = cc;
        atomicAdd(&g_cnt[cc], 1.0f);
    }

    // stage A
    {
        const int row = tx >> 2, kq = (tx & 3) * 32;
        stage_A(ea + (size_t)(bm + row) * EF + kq, row, kq, sAh, sAl);
    }

    const int warp_m = w >> 2, warp_n = w & 3;
    float acc[2][8][4];
#pragma unroll
    for (int mi = 0; mi < 2; ++mi)
#pragma unroll
        for (int ni = 0; ni < 8; ++ni)
#pragma unroll
            for (int q = 0; q < 4; ++q) acc[mi][ni][q] = 0.f;

    for (int c = 0; c < 8; ++c) {
        const int buf = c & 1;
        if (c < 7) {
            const uint32_t* src = g_BfE + (c + 1) * 4096;
#pragma unroll
            for (int i = 0; i < 2; ++i)
                CP16(sBu + ((buf ^ 1) * 4096 + i * 2048 + tx * 4) * 4, src + i * 2048 + tx * 4);
            CP_COMMIT();
            CP_WAIT(1);
        } else {
            CP_WAIT(0);
        }
        __syncthreads();
        mma_chunk(sAh, sAl, sB + buf * 4096, c, warp_m, warp_n, lane, acc);
        __syncthreads();
    }

    // epilogue: two half-width passes through padded smem, relu(+pre1), red.v4 scatter
    float* sOut = reinterpret_cast<float*>(smu);   // 128*OLD floats = 67.6KB <= 96KB
    const int g = lane >> 2, t = lane & 3;
#pragma unroll
    for (int p = 0; p < 2; ++p) {
        if ((warp_n >> 1) == p) {
#pragma unroll
            for (int mi = 0; mi < 2; ++mi) {
                int r0 = warp_m * 32 + mi * 16 + g;
#pragma unroll
                for (int ni = 0; ni < 8; ++ni) {
                    int cb = (warp_n & 1) * 64 + ni * 8 + t * 2;
                    *reinterpret_cast<float2*>(sOut + r0 * OLD + cb) =
                        make_float2(acc[mi][ni][0], acc[mi][ni][1]);
                    *reinterpret_cast<float2*>(sOut + (r0 + 8) * OLD + cb) =
                        make_float2(acc[mi][ni][2], acc[mi][ni][3]);
                }
            }
        }
        __syncthreads();
#pragma unroll
        for (int rr = 0; rr < 8; ++rr) {
            const int row = w * 8 + rr;
            const int j0 = p * 128 + lane * 4;
            const float* prow = g_pre1 + (size_t)sRow[row] * HID + j0;
            float* arow = g_aggH + (size_t)sCol[row] * HID + j0;
            float4 v = *reinterpret_cast<const float4*>(sOut + row * OLD + lane * 4);
            float4 pz = *reinterpret_cast<const float4*>(prow);
            float a0 = fmaxf(v.x + pz.x, 0.f), a1 = fmaxf(v.y + pz.y, 0.f);
            float a2 = fmaxf(v.z + pz.z, 0.f), a3 = fmaxf(v.w + pz.w, 0.f);
            asm volatile("red.global.add.v4.f32 [%0], {%1,%2,%3,%4};"
                :: "l"(arow), "f"(a0), "f"(a1), "f"(a2), "f"(a3) : "memory");
        }
        __syncthreads();
    }
}

// ---------------- node kernel (FFMA, unchanged): ----------------
__device__ __forceinline__ void load_b256(float* __restrict__ sB, const float* __restrict__ W, int tx) {
#pragma unroll
    for (int v = tx; v < 2048; v += 256) {
        int row = v >> 6, colv = v & 63;
        *reinterpret_cast<float4*>(sB + row * 256 + colv * 4) =
            *reinterpret_cast<const float4*>(W + row * 256 + colv * 4);
    }
}
__device__ __forceinline__ void load_b128(float* __restrict__ sB, const float* __restrict__ W, int tx) {
#pragma unroll
    for (int v = tx; v < 1024; v += 256) {
        int row = v >> 5, colv = v & 31;
        *reinterpret_cast<float4*>(sB + row * 128 + colv * 4) =
            *reinterpret_cast<const float4*>(W + row * 128 + colv * 4);
    }
}
template <int LDA>
__device__ __forceinline__ void gemm_chunk(const float* __restrict__ sA, const float* __restrict__ sB,
                                           int m0, int n0, int kbase, float acc[8][8]) {
#pragma unroll
    for (int kk = 0; kk < 32; ++kk) {
        const int k = kbase + kk;
        float a[8];
#pragma unroll
        for (int i = 0; i < 8; ++i) a[i] = sA[(m0 + i) * LDA + k];
        float4 bv0 = *reinterpret_cast<const float4*>(sB + kk * 256 + n0);
        float4 bv1 = *reinterpret_cast<const float4*>(sB + kk * 256 + n0 + 4);
        float b[8] = {bv0.x, bv0.y, bv0.z, bv0.w, bv1.x, bv1.y, bv1.z, bv1.w};
#pragma unroll
        for (int i = 0; i < 8; ++i)
#pragma unroll
            for (int j = 0; j < 8; ++j) acc[i][j] += a[i] * b[j];
    }
}

__global__ __launch_bounds__(256) void node_kernel(const void* __restrict__ batch,
                                                   const float* __restrict__ W4,
                                                   const float* __restrict__ b4,
                                                   float* __restrict__ out) {
    extern __shared__ float smem[];
    float* sA = smem;               // 64*256 aggH tile
    float* sH = sA + 64 * 256;      // 64*256
    float* sB = sH + 64 * 256;      // 32*256
    __shared__ float sInv[64], sFlag[64];
    __shared__ int sBat[64];

    const int tx = threadIdx.x;
    const int bm = blockIdx.x * 64;
    const int is64 = g_idx64;

    if (tx < 64) {
        int mg = min(bm + tx, NN - 1);
        float cnt = g_cnt[mg];
        sInv[tx] = 1.f / fmaxf(cnt, 1.f);
        sFlag[tx] = (cnt > 0.f) ? 1.f : 0.f;
        sBat[tx] = is64 ? (int)reinterpret_cast<const long long*>(batch)[mg]
                        : reinterpret_cast<const int*>(batch)[mg];
    }
#pragma unroll
    for (int v = tx; v < 4096; v += 256) {
        int mrow = v >> 6, cv = v & 63;
        int mg = min(bm + mrow, NN - 1);
        *reinterpret_cast<float4*>(sA + mrow * 256 + cv * 4) =
            *reinterpret_cast<const float4*>(g_aggH + (size_t)mg * HID + cv * 4);
    }
    __syncthreads();

    const int r = tx >> 5, c = tx & 31;
    const int m0 = r * 8, n0 = c * 8;
    float acc[8][8];
#pragma unroll
    for (int i = 0; i < 8; ++i)
#pragma unroll
        for (int j = 0; j < 8; ++j) acc[i][j] = 0.f;

    for (int kc = 0; kc < 8; ++kc) {
        load_b256(sB, g_W23 + (size_t)kc * 32 * 256, tx);
        __syncthreads();
        gemm_chunk<256>(sA, sB, m0, n0, kc * 32, acc);
        __syncthreads();
    }

#pragma unroll
    for (int i = 0; i < 8; ++i) {
        int mg = min(bm + m0 + i, NN - 1);
        float inv = sInv[m0 + i], fl = sFlag[m0 + i];
        const float* p3 = g_pre3 + (size_t)mg * HID + n0;
        const float* uw = g_uW3 + (size_t)sBat[m0 + i] * HID + n0;
        float4 p0 = *reinterpret_cast<const float4*>(p3);
        float4 p1 = *reinterpret_cast<const float4*>(p3 + 4);
        float4 u0 = *reinterpret_cast<const float4*>(uw);
        float4 u1 = *reinterpret_cast<const float4*>(uw + 4);
        float4 w0 = *reinterpret_cast<const float4*>(g_bW + n0);
        float4 w1 = *reinterpret_cast<const float4*>(g_bW + n0 + 4);
        float pp[8] = {p0.x, p0.y, p0.z, p0.w, p1.x, p1.y, p1.z, p1.w};
        float uu[8] = {u0.x, u0.y, u0.z, u0.w, u1.x, u1.y, u1.z, u1.w};
        float ww[8] = {w0.x, w0.y, w0.z, w0.w, w1.x, w1.y, w1.z, w1.w};
#pragma unroll
        for (int j = 0; j < 8; ++j)
            sH[(m0 + i) * 256 + n0 + j] = fmaxf(acc[i][j] * inv + pp[j] + uu[j] + ww[j] * fl, 0.f);
    }

    const int n4 = c * 4;
    float acc2[8][4];
#pragma unroll
    for (int i = 0; i < 8; ++i)
#pragma unroll
        for (int j = 0; j < 4; ++j) acc2[i][j] = 0.f;

    for (int kc = 0; kc < 8; ++kc) {
        load_b128(sB, W4 + (size_t)kc * 32 * 128, tx);
        __syncthreads();
#pragma unroll
        for (int kk = 0; kk < 32; ++kk) {
            const int k = kc * 32 + kk;
            float a[8];
#pragma unroll
            for (int i = 0; i < 8; ++i) a[i] = sH[(m0 + i) * 256 + k];
            float4 bv = *reinterpret_cast<const float4*>(sB + kk * 128 + n4);
            float b[4] = {bv.x, bv.y, bv.z, bv.w};
#pragma unroll
            for (int i = 0; i < 8; ++i)
#pragma unroll
                for (int j = 0; j < 4; ++j) acc2[i][j] += a[i] * b[j];
        }
        __syncthreads();
    }

    float4 b4v = *reinterpret_cast<const float4*>(b4 + n4);
#pragma unroll
    for (int i = 0; i < 8; ++i) {
        int mg = bm + m0 + i;
        if (mg < NN) {
            float4 o;
            o.x = acc2[i][0] + b4v.x; o.y = acc2[i][1] + b4v.y;
            o.z = acc2[i][2] + b4v.z; o.w = acc2[i][3] + b4v.w;
            *reinterpret_cast<float4*>(out + (size_t)mg * NOUT + n4) = o;
        }
    }
}

// ---------------------------------------------------------------------------
extern "C" void kernel_launch(void* const* d_in, const int* in_sizes, int n_in,
                              void* d_out, int out_size) {
    const float* x  = (const float*)d_in[0];
    const void*  ei = d_in[1];
    const float* ea = (const float*)d_in[2];
    const float* u  = (const float*)d_in[3];
    const void*  bt = d_in[4];
    const float* W1 = (const float*)d_in[5];
    const float* b1 = (const float*)d_in[6];
    const float* W2 = (const float*)d_in[7];
    const float* b2 = (const float*)d_in[8];
    const float* W3 = (const float*)d_in[9];
    const float* b3 = (const float*)d_in[10];
    const float* W4 = (const float*)d_in[11];
    const float* b4 = (const float*)d_in[12];
    float* out = (float*)d_out;

    const int smem_mma  = 24576 * 4;                              // 96 KB
    const int smem_node = (64 * 256 + 64 * 256 + 32 * 256) * 4;   // 160 KB

    cudaFuncSetAttribute(pre_mma_kernel, cudaFuncAttributeMaxDynamicSharedMemorySize, smem_mma);
    cudaFuncSetAttribute(edge_mma_kernel, cudaFuncAttributeMaxDynamicSharedMemorySize, smem_mma);
    cudaFuncSetAttribute(node_kernel, cudaFuncAttributeMaxDynamicSharedMemorySize, smem_node);

    detect_kernel<<<1, 32>>>((const unsigned int*)ei);
    zero_kernel<<<1024, 256>>>();
    prep_frag_kernel<<<192, 256>>>(W1, W3);
    prep_w23_kernel<<<256, 256>>>(W2, W3);
    prep_u_kernel<<<NG + 1, 256>>>(u, W3, b3, b2);
    pre_mma_kernel<<<dim3((NN + 127) / 128, 2), 512, smem_mma>>>(x, b1);
    edge_mma_kernel<<<NE / 128, 512, smem_mma>>>(ea, ei);
    node_kernel<<<(NN + 63) / 64, 256, smem_node>>>(bt, W4, b4, out);
}

// round 9
// speedup vs baseline: 3.7028x; 1.1375x over previous
#include <cuda_runtime.h>
#include <cuda_bf16.h>
#include <cstdint>

#define NN 50000
#define NE 640000
#define NF 128
#define EF 128
#define UF 64
#define HID 256
#define NG 64
#define NOUT 128

// ---------------- device global scratch (allocation-free) ----------------
__device__ float g_pre1[(size_t)NN * HID];   // x @ W1[0:128] + b1
__device__ float g_pre3[(size_t)NN * HID];   // x @ W3[0:128]
__device__ float g_aggH[(size_t)NN * HID];   // scatter-sum of h1
__device__ float g_cnt[NN];
__device__ float g_W23[HID * HID];           // W2 @ W3[128:384] (fp32, frag-converted later)
__device__ float g_uW3[NG * HID];            // u[g] @ W3[384:448] + b3
__device__ float g_bW[HID];                  // b2 @ W3[128:384]
// bf16 hi/lo fragment-layout weight images (m16n8k16)
__device__ uint32_t g_BfE[8 * 4096];         // W1_bot^T  : 8 chunks x [hi 2048 | lo 2048] words
__device__ uint32_t g_BfP[8 * 8192];         // [W1top|W3top]^T : 8 chunks x [hi 4096 | lo 4096]
__device__ uint32_t g_BfW23[16 * 4096];      // W23 : 16 chunks x [hi 2048 | lo 2048]
__device__ uint32_t g_BfW4[16 * 2048];       // W4  : 16 chunks x [hi 1024 | lo 1024]
__device__ int   g_idx64;

// ---------------- helpers ----------------
__device__ __forceinline__ uint32_t smem_u32(const void* p) {
    uint32_t a;
    asm("{ .reg .u64 t; cvta.to.shared.u64 t, %1; cvt.u32.u64 %0, t; }" : "=r"(a) : "l"(p));
    return a;
}
__device__ __forceinline__ uint32_t pkbf(float lo, float hi) {
    uint32_t r;
    asm("cvt.rn.bf16x2.f32 %0, %1, %2;" : "=r"(r) : "f"(hi), "f"(lo));
    return r;
}
__device__ __forceinline__ float bfr(float v) {
    return __bfloat162float(__float2bfloat16(v));
}
__device__ __forceinline__ void mma16(float d[4], const uint32_t a[4], uint32_t b0, uint32_t b1) {
    asm volatile("mma.sync.aligned.m16n8k16.row.col.f32.bf16.bf16.f32 "
                 "{%0,%1,%2,%3}, {%4,%5,%6,%7}, {%8,%9}, {%0,%1,%2,%3};"
                 : "+f"(d[0]), "+f"(d[1]), "+f"(d[2]), "+f"(d[3])
                 : "r"(a[0]), "r"(a[1]), "r"(a[2]), "r"(a[3]), "r"(b0), "r"(b1));
}

#define CP16(dst_u32, src_ptr) \
    asm volatile("cp.async.cg.shared.global [%0], [%1], 16;" :: "r"(dst_u32), "l"(src_ptr) : "memory")
#define CP_COMMIT() asm volatile("cp.async.commit_group;" ::: "memory")
#define CP_WAIT(n)  asm volatile("cp.async.wait_group %0;" :: "n"(n) : "memory")

// ---------------- detect int64/int32 indices ----------------
__global__ void detect_kernel(const unsigned int* __restrict__ ei) {
    if (threadIdx.x == 0 && blockIdx.x == 0) {
        int is64 = 1;
        for (int i = 0; i < 32; ++i)
            if (ei[2 * i + 1] != 0u) { is64 = 0; break; }
        g_idx64 = is64;
    }
}

__global__ void zero_kernel() {
    long long tid = (long long)blockIdx.x * blockDim.x + threadIdx.x;
    long long stride = (long long)gridDim.x * blockDim.x;
    float4* a4 = reinterpret_cast<float4*>(g_aggH);
    const long long n4 = (long long)NN * HID / 4;
    for (long long i = tid; i < n4; i += stride) a4[i] = make_float4(0.f, 0.f, 0.f, 0.f);
    for (long long i = tid; i < NN; i += stride) g_cnt[i] = 0.f;
}

// ---------------- prep: bf16 hi/lo fragment images for edge + pre GEMMs ----------------
__global__ void prep_frag_kernel(const float* __restrict__ W1, const float* __restrict__ W3) {
    int gid = blockIdx.x * blockDim.x + threadIdx.x;   // 0..49151
    if (gid < 16384) {
        int kp = gid >> 8, n = gid & 255;
        int k0 = kp * 2;
        float v0 = W1[(size_t)(128 + k0) * HID + n];
        float v1 = W1[(size_t)(128 + k0 + 1) * HID + n];
        float h0 = bfr(v0), h1 = bfr(v1);
        int c = k0 >> 4, kk = k0 & 15, nt = n >> 3;
        int reg = (kk >= 8) ? 1 : 0;
        int lane = (n & 7) * 4 + ((kk & 7) >> 1);
        int idx = c * 4096 + (nt * 32 + lane) * 2 + reg;
        g_BfE[idx] = pkbf(h0, h1);
        g_BfE[idx + 2048] = pkbf(v0 - h0, v1 - h1);
    } else if (gid < 49152) {
        int local = gid - 16384;
        int kp = local >> 9, n = local & 511;
        int k0 = kp * 2;
        const float* Wsrc = (n < 256) ? W1 : W3;
        int nc = n & 255;
        float v0 = Wsrc[(size_t)k0 * HID + nc];
        float v1 = Wsrc[(size_t)(k0 + 1) * HID + nc];
        float h0 = bfr(v0), h1 = bfr(v1);
        int c = k0 >> 4, kk = k0 & 15, nt = n >> 3;
        int reg = (kk >= 8) ? 1 : 0;
        int lane = (n & 7) * 4 + ((kk & 7) >> 1);
        int idx = c * 8192 + (nt * 32 + lane) * 2 + reg;
        g_BfP[idx] = pkbf(h0, h1);
        g_BfP[idx + 4096] = pkbf(v0 - h0, v1 - h1);
    }
}

// ---------------- prep: node weight frag images (after prep_w23) ----------------
// gid < 32768: W23 (K=256, N=256). else: W4 (K=256, N=128).
__global__ void prep_frag2_kernel(const float* __restrict__ W4) {
    int gid = blockIdx.x * blockDim.x + threadIdx.x;   // 0..49151
    if (gid < 32768) {
        int kp = gid >> 8, n = gid & 255;
        int k0 = kp * 2;
        float v0 = g_W23[(size_t)k0 * HID + n];
        float v1 = g_W23[(size_t)(k0 + 1) * HID + n];
        float h0 = bfr(v0), h1 = bfr(v1);
        int c = k0 >> 4, kk = k0 & 15, nt = n >> 3;
        int reg = (kk >= 8) ? 1 : 0;
        int lane = (n & 7) * 4 + ((kk & 7) >> 1);
        int idx = c * 4096 + (nt * 32 + lane) * 2 + reg;
        g_BfW23[idx] = pkbf(h0, h1);
        g_BfW23[idx + 2048] = pkbf(v0 - h0, v1 - h1);
    } else if (gid < 49152) {
        int local = gid - 32768;
        int kp = local >> 7, n = local & 127;   // kp 0..127, n 0..127
        int k0 = kp * 2;
        float v0 = W4[(size_t)k0 * NOUT + n];
        float v1 = W4[(size_t)(k0 + 1) * NOUT + n];
        float h0 = bfr(v0), h1 = bfr(v1);
        int c = k0 >> 4, kk = k0 & 15, nt = n >> 3;
        int reg = (kk >= 8) ? 1 : 0;
        int lane = (n & 7) * 4 + ((kk & 7) >> 1);
        int idx = c * 2048 + (nt * 32 + lane) * 2 + reg;
        g_BfW4[idx] = pkbf(h0, h1);
        g_BfW4[idx + 1024] = pkbf(v0 - h0, v1 - h1);
    }
}

// ---------------- prep: W23 = W2 @ W3[128:384] ----------------
__global__ void prep_w23_kernel(const float* __restrict__ W2, const float* __restrict__ W3) {
    int k = blockIdx.x, n = threadIdx.x;
    float acc = 0.f;
    for (int j = 0; j < HID; ++j)
        acc += W2[(size_t)k * HID + j] * W3[(size_t)(128 + j) * HID + n];
    g_W23[k * HID + n] = acc;
}

// ---------------- prep: uW3[g] = u[g]@W3[384:448]+b3 ; bW = b2@W3[128:384] ----------------
__global__ void prep_u_kernel(const float* __restrict__ u, const float* __restrict__ W3,
                              const float* __restrict__ b3, const float* __restrict__ b2) {
    int g = blockIdx.x, n = threadIdx.x;
    if (g < NG) {
        float acc = b3[n];
        for (int j = 0; j < UF; ++j)
            acc += u[g * UF + j] * W3[(size_t)(384 + j) * HID + n];
        g_uW3[g * HID + n] = acc;
    } else {
        float acc = 0.f;
        for (int j = 0; j < HID; ++j)
            acc += b2[j] * W3[(size_t)(128 + j) * HID + n];
        g_bW[n] = acc;
    }
}

// ---------------- shared MMA building blocks ----------------
// A frag plane: idx = ((c*8+mt)*32 + (laneT ^ (mt<<2)))*4 + reg
//   laneT=(g&7)*4+t, reg=(g>=8)+2*(kk>=8), g=row&15, mt=row>>4, t=(kk&7)>>1
__device__ __forceinline__ void stage_A(const float* __restrict__ src, int row, int kq, float scale,
                                        uint32_t* __restrict__ sAh, uint32_t* __restrict__ sAl) {
    float4 v[8];
#pragma unroll
    for (int j = 0; j < 8; ++j) v[j] = reinterpret_cast<const float4*>(src)[j];
    const float* vf = reinterpret_cast<const float*>(v);
    const int mt = row >> 4, g = row & 15;
    const int rbase = (g >= 8) ? 1 : 0;
    const int lbase = (g & 7) * 4;
#pragma unroll
    for (int pi = 0; pi < 16; ++pi) {
        float v0 = vf[2 * pi] * scale, v1 = vf[2 * pi + 1] * scale;
        float h0 = bfr(v0), h1 = bfr(v1);
        int k = kq + 2 * pi;
        int c = k >> 4, kk = k & 15;
        int reg = rbase + ((kk >= 8) ? 2 : 0);
        int lane2 = (lbase + ((kk & 7) >> 1)) ^ (mt << 2);
        int idx = ((c * 8 + mt) * 32 + lane2) * 4 + reg;
        sAh[idx] = pkbf(h0, h1);
        sAl[idx] = pkbf(v0 - h0, v1 - h1);
    }
}

// one K=16 chunk, N=256 (8 nt per warp), 3-pass
__device__ __forceinline__ void mma_chunk(const uint32_t* __restrict__ sAh,
                                          const uint32_t* __restrict__ sAl,
                                          const uint32_t* __restrict__ sB,
                                          int c, int warp_m, int warp_n, int lane,
                                          float acc[2][8][4]) {
    uint32_t ah[2][4], al[2][4];
#pragma unroll
    for (int ii = 0; ii < 2; ++ii) {
        int mt = warp_m * 2 + ii;
        int base = ((c * 8 + mt) * 32 + (lane ^ (mt << 2))) * 4;
        *reinterpret_cast<uint4*>(ah[ii]) = *reinterpret_cast<const uint4*>(sAh + base);
        *reinterpret_cast<uint4*>(al[ii]) = *reinterpret_cast<const uint4*>(sAl + base);
    }
#pragma unroll
    for (int ni = 0; ni < 8; ++ni) {
        const int nt = warp_n * 8 + ni;
        uint2 bh = *reinterpret_cast<const uint2*>(sB + (nt * 32 + lane) * 2);
        uint2 bl = *reinterpret_cast<const uint2*>(sB + 2048 + (nt * 32 + lane) * 2);
        mma16(acc[0][ni], ah[0], bh.x, bh.y);
        mma16(acc[1][ni], ah[1], bh.x, bh.y);
        mma16(acc[0][ni], al[0], bh.x, bh.y);
        mma16(acc[1][ni], al[1], bh.x, bh.y);
        mma16(acc[0][ni], ah[0], bl.x, bl.y);
        mma16(acc[1][ni], ah[1], bl.x, bl.y);
    }
}

// one K=16 chunk, N=128 (4 nt per warp), 3-pass; plane = 1024 words
__device__ __forceinline__ void mma_chunk4(const uint32_t* __restrict__ sAh,
                                           const uint32_t* __restrict__ sAl,
                                           const uint32_t* __restrict__ sB,
                                           int c, int warp_m, int warp_n, int lane,
                                           float acc[2][4][4]) {
    uint32_t ah[2][4], al[2][4];
#pragma unroll
    for (int ii = 0; ii < 2; ++ii) {
        int mt = warp_m * 2 + ii;
        int base = ((c * 8 + mt) * 32 + (lane ^ (mt << 2))) * 4;
        *reinterpret_cast<uint4*>(ah[ii]) = *reinterpret_cast<const uint4*>(sAh + base);
        *reinterpret_cast<uint4*>(al[ii]) = *reinterpret_cast<const uint4*>(sAl + base);
    }
#pragma unroll
    for (int ni = 0; ni < 4; ++ni) {
        const int nt = warp_n * 4 + ni;
        uint2 bh = *reinterpret_cast<const uint2*>(sB + (nt * 32 + lane) * 2);
        uint2 bl = *reinterpret_cast<const uint2*>(sB + 1024 + (nt * 32 + lane) * 2);
        mma16(acc[0][ni], ah[0], bh.x, bh.y);
        mma16(acc[1][ni], ah[1], bh.x, bh.y);
        mma16(acc[0][ni], al[0], bh.x, bh.y);
        mma16(acc[1][ni], al[1], bh.x, bh.y);
        mma16(acc[0][ni], ah[0], bl.x, bl.y);
        mma16(acc[1][ni], ah[1], bl.x, bl.y);
    }
}

// ---------------- pre kernel (bf16 MMA): tile 128 x 256, y selects N-half ----------------
__global__ __launch_bounds__(512, 1) void pre_mma_kernel(const float* __restrict__ x,
                                                         const float* __restrict__ b1) {
    extern __shared__ uint32_t smu[];
    uint32_t* sAh = smu;            // 8192 words
    uint32_t* sAl = smu + 8192;
    uint32_t* sB  = smu + 16384;    // 2 x 4096

    const int tx = threadIdx.x;
    const int w = tx >> 5, lane = tx & 31;
    const int bm = blockIdx.x * 128;
    const int y = blockIdx.y;
    const uint32_t sBu = smem_u32(sB);

    {
        const uint32_t* src = g_BfP + y * 2048;
#pragma unroll
        for (int seg = 0; seg < 2; ++seg)
            CP16(sBu + (seg * 2048 + tx * 4) * 4, src + seg * 4096 + tx * 4);
        CP_COMMIT();
    }
    {
        const int row = tx >> 2, kq = (tx & 3) * 32;
        int mg = min(bm + row, NN - 1);
        stage_A(x + (size_t)mg * NF + kq, row, kq, 1.f, sAh, sAl);
    }

    const int warp_m = w >> 2, warp_n = w & 3;
    float acc[2][8][4];
#pragma unroll
    for (int mi = 0; mi < 2; ++mi)
#pragma unroll
        for (int ni = 0; ni < 8; ++ni)
#pragma unroll
            for (int q = 0; q < 4; ++q) acc[mi][ni][q] = 0.f;

    for (int c = 0; c < 8; ++c) {
        const int buf = c & 1;
        if (c < 7) {
            const uint32_t* src = g_BfP + (c + 1) * 8192 + y * 2048;
#pragma unroll
            for (int seg = 0; seg < 2; ++seg)
                CP16(sBu + ((buf ^ 1) * 4096 + seg * 2048 + tx * 4) * 4, src + seg * 4096 + tx * 4);
            CP_COMMIT();
            CP_WAIT(1);
        } else {
            CP_WAIT(0);
        }
        __syncthreads();
        mma_chunk(sAh, sAl, sB + buf * 4096, c, warp_m, warp_n, lane, acc);
        __syncthreads();
    }

    const int g = lane >> 2, t = lane & 3;
    float* outp = (y == 0) ? g_pre1 : g_pre3;
#pragma unroll
    for (int mi = 0; mi < 2; ++mi) {
        int r0 = bm + warp_m * 32 + mi * 16 + g;
#pragma unroll
        for (int ni = 0; ni < 8; ++ni) {
            int cb = warp_n * 64 + ni * 8 + t * 2;
            float bb0 = 0.f, bb1 = 0.f;
            if (y == 0) { bb0 = b1[cb]; bb1 = b1[cb + 1]; }
            if (r0 < NN)
                *reinterpret_cast<float2*>(outp + (size_t)r0 * HID + cb) =
                    make_float2(acc[mi][ni][0] + bb0, acc[mi][ni][1] + bb1);
            if (r0 + 8 < NN)
                *reinterpret_cast<float2*>(outp + (size_t)(r0 + 8) * HID + cb) =
                    make_float2(acc[mi][ni][2] + bb0, acc[mi][ni][3] + bb1);
        }
    }
}

// ---------------- edge kernel (bf16 MMA): 128 edges x 256, K=128 ----------------
#define OLD 132
__global__ __launch_bounds__(512, 1) void edge_mma_kernel(const float* __restrict__ ea,
                                                          const void* __restrict__ eidx) {
    extern __shared__ uint32_t smu[];
    uint32_t* sAh = smu;
    uint32_t* sAl = smu + 8192;
    uint32_t* sB  = smu + 16384;
    __shared__ int sRow[128], sCol[128];

    const int tx = threadIdx.x;
    const int w = tx >> 5, lane = tx & 31;
    const int bm = blockIdx.x * 128;
    const int is64 = g_idx64;
    const uint32_t sBu = smem_u32(sB);

    {
        const uint32_t* src = g_BfE;
#pragma unroll
        for (int i = 0; i < 2; ++i)
            CP16(sBu + (i * 2048 + tx * 4) * 4, src + i * 2048 + tx * 4);
        CP_COMMIT();
    }

    if (tx < 128) {
        long long e = bm + tx;
        int rr, cc;
        if (is64) {
            rr = (int)reinterpret_cast<const long long*>(eidx)[e];
            cc = (int)reinterpret_cast<const long long*>(eidx)[NE + e];
        } else {
            rr = reinterpret_cast<const int*>(eidx)[e];
            cc = reinterpret_cast<const int*>(eidx)[NE + e];
        }
        sRow[tx] = rr; sCol[tx] = cc;
        atomicAdd(&g_cnt[cc], 1.0f);
    }

    {
        const int row = tx >> 2, kq = (tx & 3) * 32;
        stage_A(ea + (size_t)(bm + row) * EF + kq, row, kq, 1.f, sAh, sAl);
    }

    const int warp_m = w >> 2, warp_n = w & 3;
    float acc[2][8][4];
#pragma unroll
    for (int mi = 0; mi < 2; ++mi)
#pragma unroll
        for (int ni = 0; ni < 8; ++ni)
#pragma unroll
            for (int q = 0; q < 4; ++q) acc[mi][ni][q] = 0.f;

    for (int c = 0; c < 8; ++c) {
        const int buf = c & 1;
        if (c < 7) {
            const uint32_t* src = g_BfE + (c + 1) * 4096;
#pragma unroll
            for (int i = 0; i < 2; ++i)
                CP16(sBu + ((buf ^ 1) * 4096 + i * 2048 + tx * 4) * 4, src + i * 2048 + tx * 4);
            CP_COMMIT();
            CP_WAIT(1);
        } else {
            CP_WAIT(0);
        }
        __syncthreads();
        mma_chunk(sAh, sAl, sB + buf * 4096, c, warp_m, warp_n, lane, acc);
        __syncthreads();
    }

    float* sOut = reinterpret_cast<float*>(smu);
    const int g = lane >> 2, t = lane & 3;
#pragma unroll
    for (int p = 0; p < 2; ++p) {
        if ((warp_n >> 1) == p) {
#pragma unroll
            for (int mi = 0; mi < 2; ++mi) {
                int r0 = warp_m * 32 + mi * 16 + g;
#pragma unroll
                for (int ni = 0; ni < 8; ++ni) {
                    int cb = (warp_n & 1) * 64 + ni * 8 + t * 2;
                    *reinterpret_cast<float2*>(sOut + r0 * OLD + cb) =
                        make_float2(acc[mi][ni][0], acc[mi][ni][1]);
                    *reinterpret_cast<float2*>(sOut + (r0 + 8) * OLD + cb) =
                        make_float2(acc[mi][ni][2], acc[mi][ni][3]);
                }
            }
        }
        __syncthreads();
#pragma unroll
        for (int rr = 0; rr < 8; ++rr) {
            const int row = w * 8 + rr;
            const int j0 = p * 128 + lane * 4;
            const float* prow = g_pre1 + (size_t)sRow[row] * HID + j0;
            float* arow = g_aggH + (size_t)sCol[row] * HID + j0;
            float4 v = *reinterpret_cast<const float4*>(sOut + row * OLD + lane * 4);
            float4 pz = *reinterpret_cast<const float4*>(prow);
            float a0 = fmaxf(v.x + pz.x, 0.f), a1 = fmaxf(v.y + pz.y, 0.f);
            float a2 = fmaxf(v.z + pz.z, 0.f), a3 = fmaxf(v.w + pz.w, 0.f);
            asm volatile("red.global.add.v4.f32 [%0], {%1,%2,%3,%4};"
                :: "l"(arow), "f"(a0), "f"(a1), "f"(a2), "f"(a3) : "memory");
        }
        __syncthreads();
    }
}

// ---------------- node kernel (bf16 MMA): 128 nodes x 256, K=256, then L4 ----------------
// A = aggH*inv (mean folded into staging); t = A @ W23
// hid = relu(t + pre3 + uW3[bat] + bW*flag)  -> re-staged as A frags
// out = hid @ W4 + b4
__global__ __launch_bounds__(512, 1) void node_mma_kernel(const void* __restrict__ batch,
                                                          const float* __restrict__ b4,
                                                          float* __restrict__ out) {
    extern __shared__ uint32_t smu[];
    uint32_t* sAh = smu;            // 16384 words (16 chunks)
    uint32_t* sAl = smu + 16384;    // 16384
    uint32_t* sB  = smu + 32768;    // 2 x 4096
    __shared__ int sBat[128];
    __shared__ float sFlag[128];

    const int tx = threadIdx.x;
    const int w = tx >> 5, lane = tx & 31;
    const int bm = blockIdx.x * 128;
    const int is64 = g_idx64;
    const uint32_t sBu = smem_u32(sB);

    // first W23 chunk
    {
#pragma unroll
        for (int i = 0; i < 2; ++i)
            CP16(sBu + (i * 2048 + tx * 4) * 4, g_BfW23 + i * 2048 + tx * 4);
        CP_COMMIT();
    }

    if (tx < 128) {
        int mg = min(bm + tx, NN - 1);
        float cnt = g_cnt[mg];
        sFlag[tx] = (cnt > 0.f) ? 1.f : 0.f;
        sBat[tx] = is64 ? (int)reinterpret_cast<const long long*>(batch)[mg]
                        : reinterpret_cast<const int*>(batch)[mg];
    }

    // stage A = aggH * inv  (two 32-K spans per thread; K=256)
    {
        const int row = tx >> 2;
        int mg = min(bm + row, NN - 1);
        float inv = 1.f / fmaxf(g_cnt[mg], 1.f);
        const float* src = g_aggH + (size_t)mg * HID;
        int kq0 = (tx & 3) * 32;
        stage_A(src + kq0, row, kq0, inv, sAh, sAl);
        stage_A(src + kq0 + 128, row, kq0 + 128, inv, sAh, sAl);
    }

    const int warp_m = w >> 2, warp_n = w & 3;
    float acc[2][8][4];
#pragma unroll
    for (int mi = 0; mi < 2; ++mi)
#pragma unroll
        for (int ni = 0; ni < 8; ++ni)
#pragma unroll
            for (int q = 0; q < 4; ++q) acc[mi][ni][q] = 0.f;

    for (int c = 0; c < 16; ++c) {
        const int buf = c & 1;
        if (c < 15) {
            const uint32_t* src = g_BfW23 + (c + 1) * 4096;
#pragma unroll
            for (int i = 0; i < 2; ++i)
                CP16(sBu + ((buf ^ 1) * 4096 + i * 2048 + tx * 4) * 4, src + i * 2048 + tx * 4);
            CP_COMMIT();
            CP_WAIT(1);
        } else {
            CP_WAIT(0);
        }
        __syncthreads();
        mma_chunk(sAh, sAl, sB + buf * 4096, c, warp_m, warp_n, lane, acc);
        __syncthreads();
    }

    // issue first W4 chunk into buf 0 (all warps past last mma read of buf0)
    CP16(sBu + (tx * 4) * 4, g_BfW4 + tx * 4);
    CP_COMMIT();

    // L3 epilogue: hid = relu(acc + pre3 + uW3 + bW*flag), pack into A frags
    const int g = lane >> 2, t = lane & 3;
#pragma unroll
    for (int mi = 0; mi < 2; ++mi) {
        const int mt = warp_m * 2 + mi;
        const int rA = warp_m * 32 + mi * 16 + g;       // rows rA, rA+8
        const int mgA = min(bm + rA, NN - 1);
        const int mgB = min(bm + rA + 8, NN - 1);
        const float flA = sFlag[rA], flB = sFlag[rA + 8];
        const float* p3A = g_pre3 + (size_t)mgA * HID;
        const float* p3B = g_pre3 + (size_t)mgB * HID;
        const float* uwA = g_uW3 + (size_t)sBat[rA] * HID;
        const float* uwB = g_uW3 + (size_t)sBat[rA + 8] * HID;
#pragma unroll
        for (int ni = 0; ni < 8; ++ni) {
            int cb = warp_n * 64 + ni * 8 + t * 2;
            int c = cb >> 4, kk = cb & 15;
            int lane2 = ((g & 7) * 4 + ((kk & 7) >> 1)) ^ (mt << 2);
            int idx = ((c * 8 + mt) * 32 + lane2) * 4 + ((kk >= 8) ? 2 : 0);
            float2 bw = *reinterpret_cast<const float2*>(g_bW + cb);
            {   // row rA (g<8 -> rbase 0)
                float2 p3 = *reinterpret_cast<const float2*>(p3A + cb);
                float2 uw = *reinterpret_cast<const float2*>(uwA + cb);
                float h0 = fmaxf(acc[mi][ni][0] + p3.x + uw.x + bw.x * flA, 0.f);
                float h1 = fmaxf(acc[mi][ni][1] + p3.y + uw.y + bw.y * flA, 0.f);
                float b0 = bfr(h0), b1v = bfr(h1);
                sAh[idx] = pkbf(b0, b1v);
                sAl[idx] = pkbf(h0 - b0, h1 - b1v);
            }
            {   // row rA+8 (rbase 1)
                float2 p3 = *reinterpret_cast<const float2*>(p3B + cb);
                float2 uw = *reinterpret_cast<const float2*>(uwB + cb);
                float h0 = fmaxf(acc[mi][ni][2] + p3.x + uw.x + bw.x * flB, 0.f);
                float h1 = fmaxf(acc[mi][ni][3] + p3.y + uw.y + bw.y * flB, 0.f);
                float b0 = bfr(h0), b1v = bfr(h1);
                sAh[idx + 1] = pkbf(b0, b1v);
                sAl[idx + 1] = pkbf(h0 - b0, h1 - b1v);
            }
        }
    }
    __syncthreads();

    // L4: hid @ W4 (K=256, N=128)
    float acc2[2][4][4];
#pragma unroll
    for (int mi = 0; mi < 2; ++mi)
#pragma unroll
        for (int ni = 0; ni < 4; ++ni)
#pragma unroll
            for (int q = 0; q < 4; ++q) acc2[mi][ni][q] = 0.f;

    for (int c = 0; c < 16; ++c) {
        const int buf = c & 1;
        if (c < 15) {
            CP16(sBu + ((buf ^ 1) * 4096 + tx * 4) * 4, g_BfW4 + (c + 1) * 2048 + tx * 4);
            CP_COMMIT();
            CP_WAIT(1);
        } else {
            CP_WAIT(0);
        }
        __syncthreads();
        mma_chunk4(sAh, sAl, sB + buf * 4096, c, warp_m, warp_n, lane, acc2);
        __syncthreads();
    }

    // L4 epilogue: register-direct stores
#pragma unroll
    for (int mi = 0; mi < 2; ++mi) {
        int r0 = bm + warp_m * 32 + mi * 16 + g;
#pragma unroll
        for (int ni = 0; ni < 4; ++ni) {
            int cb = warp_n * 32 + ni * 8 + t * 2;
            float2 bb = *reinterpret_cast<const float2*>(b4 + cb);
            if (r0 < NN)
                *reinterpret_cast<float2*>(out + (size_t)r0 * NOUT + cb) =
                    make_float2(acc2[mi][ni][0] + bb.x, acc2[mi][ni][1] + bb.y);
            if (r0 + 8 < NN)
                *reinterpret_cast<float2*>(out + (size_t)(r0 + 8) * NOUT + cb) =
                    make_float2(acc2[mi][ni][2] + bb.x, acc2[mi][ni][3] + bb.y);
        }
    }
}

// ---------------------------------------------------------------------------
extern "C" void kernel_launch(void* const* d_in, const int* in_sizes, int n_in,
                              void* d_out, int out_size) {
    const float* x  = (const float*)d_in[0];
    const void*  ei = d_in[1];
    const float* ea = (const float*)d_in[2];
    const float* u  = (const float*)d_in[3];
    const void*  bt = d_in[4];
    const float* W1 = (const float*)d_in[5];
    const float* b1 = (const float*)d_in[6];
    const float* W2 = (const float*)d_in[7];
    const float* b2 = (const float*)d_in[8];
    const float* W3 = (const float*)d_in[9];
    const float* b3 = (const float*)d_in[10];
    const float* W4 = (const float*)d_in[11];
    const float* b4 = (const float*)d_in[12];
    float* out = (float*)d_out;

    const int smem_mma  = 24576 * 4;   // 96 KB (pre/edge)
    const int smem_node = 40960 * 4;   // 160 KB

    cudaFuncSetAttribute(pre_mma_kernel, cudaFuncAttributeMaxDynamicSharedMemorySize, smem_mma);
    cudaFuncSetAttribute(edge_mma_kernel, cudaFuncAttributeMaxDynamicSharedMemorySize, smem_mma);
    cudaFuncSetAttribute(node_mma_kernel, cudaFuncAttributeMaxDynamicSharedMemorySize, smem_node);

    detect_kernel<<<1, 32>>>((const unsigned int*)ei);
    zero_kernel<<<1024, 256>>>();
    prep_frag_kernel<<<192, 256>>>(W1, W3);
    prep_w23_kernel<<<256, 256>>>(W2, W3);
    prep_frag2_kernel<<<192, 256>>>(W4);
    prep_u_kernel<<<NG + 1, 256>>>(u, W3, b3, b2);
    pre_mma_kernel<<<dim3((NN + 127) / 128, 2), 512, smem_mma>>>(x, b1);
    edge_mma_kernel<<<NE / 128, 512, smem_mma>>>(ea, ei);
    node_mma_kernel<<<(NN + 127) / 128, 512, smem_node>>>(bt, b4, out);
}